// round 10
// baseline (speedup 1.0000x reference)
#include <cuda_runtime.h>
#include <cuda_bf16.h>
#include <cstdint>

#define BS   2
#define SEQ  2048
#define DIM  1024
#define NH   16
#define HD   64
#define PREFIX 256
#define MROWS (BS*SEQ)
#define KT   (3*DIM)          // tripled K for bf16-split GEMM

// ------------------------- device scratch (no allocs) -----------------------
__device__ __nv_bfloat16 g_Qh[BS*NH*SEQ*HD];
__device__ __nv_bfloat16 g_Ql[BS*NH*SEQ*HD];
__device__ __nv_bfloat16 g_Kh[BS*NH*SEQ*HD];
__device__ __nv_bfloat16 g_Kl[BS*NH*SEQ*HD];
__device__ __nv_bfloat16 g_Vh[BS*NH*SEQ*HD];
__device__ __nv_bfloat16 g_Vl[BS*NH*SEQ*HD];
__device__ __nv_bfloat16 g_x3 [MROWS*KT];      // x split-3      (4096 x 3072)
__device__ __nv_bfloat16 g_w3 [3*DIM*KT];      // qkv_w split-3  (3072 x 3072)
__device__ __nv_bfloat16 g_o3 [MROWS*KT];      // attn out split (4096 x 3072)
__device__ __nv_bfloat16 g_pw3[DIM*KT];        // proj_w split-3 (1024 x 3072)

// ------------------------- portable PTX helpers (sm_80+) --------------------
__device__ __forceinline__ uint32_t smem_u32(const void* p) {
    uint32_t a;
    asm("{ .reg .u64 t; cvta.to.shared.u64 t, %1; cvt.u32.u64 %0, t; }" : "=r"(a) : "l"(p));
    return a;
}
__device__ __forceinline__ void cp16(uint32_t saddr, const void* g) {
    asm volatile("cp.async.cg.shared.global [%0], [%1], 16;" :: "r"(saddr), "l"(g));
}
#define CP_COMMIT()  asm volatile("cp.async.commit_group;" ::: "memory")
#define CP_WAIT(n)   asm volatile("cp.async.wait_group %0;" :: "n"(n) : "memory")

__device__ __forceinline__ void ldsm4(uint32_t* r, uint32_t addr) {
    asm volatile("ldmatrix.sync.aligned.m8n8.x4.shared.b16 {%0,%1,%2,%3}, [%4];"
                 : "=r"(r[0]), "=r"(r[1]), "=r"(r[2]), "=r"(r[3]) : "r"(addr));
}
__device__ __forceinline__ void ldsm4t(uint32_t* r, uint32_t addr) {
    asm volatile("ldmatrix.sync.aligned.m8n8.x4.trans.shared.b16 {%0,%1,%2,%3}, [%4];"
                 : "=r"(r[0]), "=r"(r[1]), "=r"(r[2]), "=r"(r[3]) : "r"(addr));
}
__device__ __forceinline__ void mma16816(float* c, const uint32_t* a, uint32_t b0, uint32_t b1) {
    asm volatile("mma.sync.aligned.m16n8k16.row.col.f32.bf16.bf16.f32 "
                 "{%0,%1,%2,%3}, {%4,%5,%6,%7}, {%8,%9}, {%0,%1,%2,%3};"
                 : "+f"(c[0]), "+f"(c[1]), "+f"(c[2]), "+f"(c[3])
                 : "r"(a[0]), "r"(a[1]), "r"(a[2]), "r"(a[3]), "r"(b0), "r"(b1));
}
__device__ __forceinline__ uint32_t pk2(__nv_bfloat16 lo, __nv_bfloat16 hi) {
    __nv_bfloat162 t; t.x = lo; t.y = hi;
    return *(uint32_t*)&t;
}

// ---------------------------------------------------------------------------
// split-3 conversion: fp32 -> bf16 triplets.
// MODE 0 (A side): [hi, lo, hi]   MODE 1 (B side): [hi, hi, lo]
// ---------------------------------------------------------------------------
template<int MODE>
__global__ __launch_bounds__(256) void split3_kernel(const float* __restrict__ src,
                                                     __nv_bfloat16* __restrict__ dst,
                                                     int n4)
{
    int i = blockIdx.x * blockDim.x + threadIdx.x;
    if (i >= n4) return;
    float4 v = ((const float4*)src)[i];
    float xs[4] = {v.x, v.y, v.z, v.w};
    __nv_bfloat16 t[12];
#pragma unroll
    for (int j = 0; j < 4; j++) {
        __nv_bfloat16 hi = __float2bfloat16(xs[j]);
        __nv_bfloat16 lo = __float2bfloat16(xs[j] - __bfloat162float(hi));
        t[3*j+0] = hi;
        t[3*j+1] = (MODE == 0) ? lo : hi;
        t[3*j+2] = (MODE == 0) ? hi : lo;
    }
    uint2* dp = (uint2*)(dst + (size_t)i * 12);
    const uint2* tp = (const uint2*)t;
    dp[0] = tp[0]; dp[1] = tp[1]; dp[2] = tp[2];
}

// ---------------------------------------------------------------------------
// HMMA bf16 GEMM v3: CTA 256x128, 8 warps in 4x2 grid, warp tile 64x64
// (smem intensity = 16 MAC/B -> crossbar no longer caps tensor at 50%).
// 3-stage cp.async pipeline, 64B rows + XOR swizzle, 72KB DYNAMIC smem.
// EPI 0: write Q/K/V as bf16 hi/lo pairs (Q * 0.125)   EPI 1: out = C + bias
// ---------------------------------------------------------------------------
#define GEMM_SMEM_BYTES (3 * (256*64 + 128*64))   // 73728
template<int EPI>
__global__ __launch_bounds__(256, 1) void mma_gemm(const __nv_bfloat16* __restrict__ A3,
                                                   const __nv_bfloat16* __restrict__ B3,
                                                   const float* __restrict__ bias,
                                                   float* __restrict__ Cout)
{
    extern __shared__ __align__(16) char dynsmem[];

    const int tid  = threadIdx.x;
    const int wid  = tid >> 5, lane = tid & 31;
    const int wm   = wid & 3,  wn   = wid >> 2;      // 4x2 warp grid
    const int bn   = blockIdx.x, bm = blockIdx.y;
    const int NCH  = KT / 32;                        // 96 chunks
    const uint32_t STA = 256 * 64;                   // A stage bytes = 16384
    const uint32_t STB = 128 * 64;                   // B stage bytes =  8192

    const char* Ab = (const char*)(A3 + (size_t)bm * 256 * KT);
    const char* Bb = (const char*)(B3 + (size_t)bn * 128 * KT);

    const uint32_t sA0 = smem_u32(dynsmem);
    const uint32_t sB0 = sA0 + 3 * STA;

    float acc[4][8][4];
#pragma unroll
    for (int i = 0; i < 4; i++)
#pragma unroll
        for (int j = 0; j < 8; j++)
#pragma unroll
            for (int k = 0; k < 4; k++) acc[i][j][k] = 0.f;

    // per chunk: A = 1024 segs (4/thread), B = 512 segs (2/thread)
#define LOAD_TILE(c, st)                                                           \
    {                                                                              \
        int koff = (c) * 64;                                                       \
        _Pragma("unroll")                                                          \
        for (int i = 0; i < 4; i++) {                                              \
            int idx = tid + i * 256;                                               \
            int row = idx >> 2, seg = idx & 3;                                     \
            int pseg = seg ^ ((row >> 1) & 3);                                     \
            cp16(sA0 + (uint32_t)((st) * STA + row * 64 + pseg * 16),              \
                 Ab + (size_t)row * (KT*2) + koff + seg * 16);                     \
        }                                                                          \
        _Pragma("unroll")                                                          \
        for (int i = 0; i < 2; i++) {                                              \
            int idx = tid + i * 256;                                               \
            int row = idx >> 2, seg = idx & 3;                                     \
            int pseg = seg ^ ((row >> 1) & 3);                                     \
            cp16(sB0 + (uint32_t)((st) * STB + row * 64 + pseg * 16),              \
                 Bb + (size_t)row * (KT*2) + koff + seg * 16);                     \
        }                                                                          \
    }

    LOAD_TILE(0, 0); CP_COMMIT();
    LOAD_TILE(1, 1); CP_COMMIT();

    const int lrow = lane & 15;
    const int lhalf = lane >> 4;                     // 0/1 -> +16B column

    int st = 0;                                      // stage of chunk c
    for (int c = 0; c < NCH; c++) {
        CP_WAIT(1);                                  // stage of chunk c complete
        __syncthreads();                             // everyone done with c-1 too

        if (c + 2 < NCH) {
            int st2 = (st + 2 >= 3) ? st - 1 : st + 2;
            LOAD_TILE(c + 2, st2);
        }
        CP_COMMIT();

        uint32_t abase = sA0 + st * STA;
        uint32_t bbase = sB0 + st * STB;
#pragma unroll
        for (int kg = 0; kg < 2; kg++) {
            uint32_t a[4][4], b[4][4];
            int lseg = kg * 2 + lhalf;
#pragma unroll
            for (int mt = 0; mt < 4; mt++) {
                int row = wm*64 + mt*16 + lrow;
                ldsm4(a[mt], abase + (uint32_t)(row * 64 + (lseg ^ ((row >> 1) & 3)) * 16));
            }
#pragma unroll
            for (int p = 0; p < 4; p++) {
                int row = wn*64 + p*16 + lrow;
                ldsm4(b[p], bbase + (uint32_t)(row * 64 + (lseg ^ ((row >> 1) & 3)) * 16));
            }
#pragma unroll
            for (int mt = 0; mt < 4; mt++)
#pragma unroll
                for (int nt = 0; nt < 8; nt++) {
                    int p = nt >> 1, q = nt & 1;
                    mma16816(acc[mt][nt], a[mt], b[p][q], b[p][q + 2]);
                }
        }
        st = (st + 1 >= 3) ? 0 : st + 1;
    }

#pragma unroll
    for (int mt = 0; mt < 4; mt++) {
#pragma unroll
        for (int nt = 0; nt < 8; nt++) {
            int m0 = bm * 256 + wm * 64 + mt * 16 + (lane >> 2);
            int n0 = bn * 128 + wn * 64 + nt * 8 + 2 * (lane & 3);
            float c0 = acc[mt][nt][0], c1 = acc[mt][nt][1];
            float c2 = acc[mt][nt][2], c3 = acc[mt][nt][3];
            if (EPI == 0) {
                int part = n0 >> 10;
                __nv_bfloat16 *dh = (part == 0) ? g_Qh : (part == 1) ? g_Kh : g_Vh;
                __nv_bfloat16 *dl = (part == 0) ? g_Ql : (part == 1) ? g_Kl : g_Vl;
                float scl = (part == 0) ? 0.125f : 1.0f;
                int head = (n0 & 1023) >> 6, d = n0 & 63;
#pragma unroll
                for (int rr = 0; rr < 2; rr++) {
                    int m = m0 + rr * 8;
                    int bi = m >> 11, s = m & (SEQ - 1);
                    float v0 = (rr ? c2 : c0) * scl, v1 = (rr ? c3 : c1) * scl;
                    __nv_bfloat16 h0 = __float2bfloat16(v0);
                    __nv_bfloat16 l0 = __float2bfloat16(v0 - __bfloat162float(h0));
                    __nv_bfloat16 h1 = __float2bfloat16(v1);
                    __nv_bfloat16 l1 = __float2bfloat16(v1 - __bfloat162float(h1));
                    size_t idx = (((size_t)(bi*NH + head))*SEQ + s)*HD + d;
                    *(uint32_t*)&dh[idx] = pk2(h0, h1);
                    *(uint32_t*)&dl[idx] = pk2(l0, l1);
                }
            } else {
                float2 bv = *(const float2*)&bias[n0];
                *(float2*)&Cout[(size_t)m0 * DIM + n0]       = make_float2(c0 + bv.x, c1 + bv.y);
                *(float2*)&Cout[(size_t)(m0 + 8) * DIM + n0] = make_float2(c2 + bv.x, c3 + bv.y);
            }
        }
    }
}

// ---------------------------------------------------------------------------
// HMMA flash attention (UNCHANGED from round 9 — known-good).
// ---------------------------------------------------------------------------
__global__ __launch_bounds__(128) void attn_mma()
{
    __shared__ __align__(16) __nv_bfloat16 sQh[64*64];
    __shared__ __align__(16) __nv_bfloat16 sQl[64*64];
    __shared__ __align__(16) __nv_bfloat16 sKh[2][32*64];
    __shared__ __align__(16) __nv_bfloat16 sKl[2][32*64];
    __shared__ __align__(16) __nv_bfloat16 sVh[2][32*64];
    __shared__ __align__(16) __nv_bfloat16 sVl[2][32*64];

    const int qi  = blockIdx.x;
    const int bh  = blockIdx.y;
    const int b   = bh >> 4, h = bh & 15;
    const int tid = threadIdx.x, w = tid >> 5, lane = tid & 31;
    const int qbase = qi * 64;

    const size_t base = (size_t)bh * SEQ * HD;
    const uint32_t qh0 = smem_u32(sQh), ql0 = smem_u32(sQl);
    const uint32_t kh0 = smem_u32(sKh), kl0 = smem_u32(sKl);
    const uint32_t vh0 = smem_u32(sVh), vl0 = smem_u32(sVl);
    const uint32_t KVST = 32 * 128;

    for (int i = tid; i < 512; i += 128) {
        int r = i >> 3, seg = i & 7;
        int pseg = seg ^ (r & 7);
        const char* gq = (const char*)(g_Qh + base + (size_t)(qbase + r) * HD);
        const char* gl = (const char*)(g_Ql + base + (size_t)(qbase + r) * HD);
        cp16(qh0 + (uint32_t)(r * 128 + pseg * 16), gq + seg * 16);
        cp16(ql0 + (uint32_t)(r * 128 + pseg * 16), gl + seg * 16);
    }
    CP_COMMIT();

#define LOADKV(ch, st)                                                              \
    {                                                                               \
        int kb = (ch) * 32;                                                         \
        _Pragma("unroll")                                                           \
        for (int i = tid; i < 256; i += 128) {                                      \
            int r = i >> 3, seg = i & 7;                                            \
            int pseg = seg ^ (r & 7);                                               \
            size_t gidx = base + (size_t)(kb + r) * HD;                             \
            uint32_t so = (uint32_t)((st) * KVST + r * 128 + pseg * 16);            \
            cp16(kh0 + so, (const char*)(g_Kh + gidx) + seg * 16);                  \
            cp16(kl0 + so, (const char*)(g_Kl + gidx) + seg * 16);                  \
            cp16(vh0 + so, (const char*)(g_Vh + gidx) + seg * 16);                  \
            cp16(vl0 + so, (const char*)(g_Vl + gidx) + seg * 16);                  \
        }                                                                           \
    }

    const int nch = (qi < 4) ? 8 : 2 * (qi + 1);
    LOADKV(0, 0); CP_COMMIT();

    float o[8][4];
#pragma unroll
    for (int i = 0; i < 8; i++)
#pragma unroll
        for (int j = 0; j < 4; j++) o[i][j] = 0.f;
    float mi[2] = {-1e30f, -1e30f}, li[2] = {0.f, 0.f};

    const int lrow  = lane & 15;
    const int lhalf = lane >> 4;

    for (int ch = 0; ch < nch; ch++) {
        CP_WAIT(0);
        __syncthreads();
        if (ch + 1 < nch) { LOADKV(ch + 1, (ch + 1) & 1); }
        CP_COMMIT();

        const int kbase = ch * 32;
        const uint32_t kvoff = (uint32_t)((ch & 1) * KVST);

        float s[4][4];
#pragma unroll
        for (int nt = 0; nt < 4; nt++)
#pragma unroll
            for (int j = 0; j < 4; j++) s[nt][j] = 0.f;

#pragma unroll
        for (int kg = 0; kg < 4; kg++) {
            int lseg = kg * 2 + lhalf;
            uint32_t aH[4], aL[4], bH[2][4], bL[2][4];
            {
                int row = w*16 + lrow;
                uint32_t ao = (uint32_t)(row * 128 + (lseg ^ (row & 7)) * 16);
                ldsm4(aH, qh0 + ao);
                ldsm4(aL, ql0 + ao);
            }
#pragma unroll
            for (int p = 0; p < 2; p++) {
                int row = p*16 + lrow;
                uint32_t bo = kvoff + (uint32_t)(row * 128 + (lseg ^ (row & 7)) * 16);
                ldsm4(bH[p], kh0 + bo);
                ldsm4(bL[p], kl0 + bo);
            }
#pragma unroll
            for (int nt = 0; nt < 4; nt++) {
                int p = nt >> 1, q = nt & 1;
                mma16816(s[nt], aH, bH[p][q], bH[p][q+2]);
                mma16816(s[nt], aL, bH[p][q], bH[p][q+2]);
                mma16816(s[nt], aH, bL[p][q], bL[p][q+2]);
            }
        }

        if (kbase >= PREFIX && kbase + 31 > qbase) {
            int q0 = qbase + w*16 + (lane >> 2);
#pragma unroll
            for (int nt = 0; nt < 4; nt++) {
                int k0 = kbase + nt*8 + 2*(lane & 3);
                if (k0     > q0)     s[nt][0] = -1e30f;
                if (k0 + 1 > q0)     s[nt][1] = -1e30f;
                if (k0     > q0 + 8) s[nt][2] = -1e30f;
                if (k0 + 1 > q0 + 8) s[nt][3] = -1e30f;
            }
        }

#pragma unroll
        for (int rr = 0; rr < 2; rr++) {
            float mx = -1e30f;
#pragma unroll
            for (int nt = 0; nt < 4; nt++)
                mx = fmaxf(mx, fmaxf(s[nt][2*rr], s[nt][2*rr+1]));
            mx = fmaxf(mx, __shfl_xor_sync(0xffffffffu, mx, 1));
            mx = fmaxf(mx, __shfl_xor_sync(0xffffffffu, mx, 2));
            float mnew  = fmaxf(mi[rr], mx);
            float alpha = __expf(mi[rr] - mnew);
            float rs = 0.f;
#pragma unroll
            for (int nt = 0; nt < 4; nt++) {
                float p0 = __expf(s[nt][2*rr]   - mnew);
                float p1 = __expf(s[nt][2*rr+1] - mnew);
                s[nt][2*rr] = p0; s[nt][2*rr+1] = p1;
                rs += p0 + p1;
            }
            rs += __shfl_xor_sync(0xffffffffu, rs, 1);
            rs += __shfl_xor_sync(0xffffffffu, rs, 2);
            li[rr] = li[rr] * alpha + rs;
            mi[rr] = mnew;
#pragma unroll
            for (int dn = 0; dn < 8; dn++) {
                o[dn][2*rr] *= alpha; o[dn][2*rr+1] *= alpha;
            }
        }

#pragma unroll
        for (int kt = 0; kt < 2; kt++) {
            uint32_t pH[4], pL[4];
#pragma unroll
            for (int half = 0; half < 2; half++) {
                float* sv = s[2*kt + half];
                __nv_bfloat16 h0 = __float2bfloat16(sv[0]);
                __nv_bfloat16 h1 = __float2bfloat16(sv[1]);
                __nv_bfloat16 h2 = __float2bfloat16(sv[2]);
                __nv_bfloat16 h3 = __float2bfloat16(sv[3]);
                __nv_bfloat16 l0 = __float2bfloat16(sv[0] - __bfloat162float(h0));
                __nv_bfloat16 l1 = __float2bfloat16(sv[1] - __bfloat162float(h1));
                __nv_bfloat16 l2 = __float2bfloat16(sv[2] - __bfloat162float(h2));
                __nv_bfloat16 l3 = __float2bfloat16(sv[3] - __bfloat162float(h3));
                pH[half*2+0] = pk2(h0, h1); pH[half*2+1] = pk2(h2, h3);
                pL[half*2+0] = pk2(l0, l1); pL[half*2+1] = pk2(l2, l3);
            }
#pragma unroll
            for (int p4 = 0; p4 < 4; p4++) {
                int row = kt*16 + lrow;
                int lseg = p4*2 + lhalf;
                uint32_t vo = kvoff + (uint32_t)(row * 128 + (lseg ^ (row & 7)) * 16);
                uint32_t vH[4], vL[4];
                ldsm4t(vH, vh0 + vo);
                ldsm4t(vL, vl0 + vo);
                mma16816(o[2*p4],   pH, vH[0], vH[1]);
                mma16816(o[2*p4],   pL, vH[0], vH[1]);
                mma16816(o[2*p4],   pH, vL[0], vL[1]);
                mma16816(o[2*p4+1], pH, vH[2], vH[3]);
                mma16816(o[2*p4+1], pL, vH[2], vH[3]);
                mma16816(o[2*p4+1], pH, vL[2], vL[3]);
            }
        }
    }

#pragma unroll
    for (int dn = 0; dn < 8; dn++) {
        int d0 = dn*8 + 2*(lane & 3);
#pragma unroll
        for (int rr = 0; rr < 2; rr++) {
            int row = qbase + w*16 + (lane >> 2) + rr*8;
            float inv = 1.0f / li[rr];
            float v0 = o[dn][2*rr]   * inv;
            float v1 = o[dn][2*rr+1] * inv;
            __nv_bfloat16 h0 = __float2bfloat16(v0);
            __nv_bfloat16 l0 = __float2bfloat16(v0 - __bfloat162float(h0));
            __nv_bfloat16 h1 = __float2bfloat16(v1);
            __nv_bfloat16 l1 = __float2bfloat16(v1 - __bfloat162float(h1));
            size_t off = (size_t)(b*SEQ + row) * KT + (size_t)3 * (h*HD + d0);
            *(uint32_t*)&g_o3[off]     = pk2(h0, l0);
            *(uint32_t*)&g_o3[off + 2] = pk2(h0, h1);
            *(uint32_t*)&g_o3[off + 4] = pk2(l1, h1);
        }
    }
}

// ---------------------------------------------------------------------------
extern "C" void kernel_launch(void* const* d_in, const int* in_sizes, int n_in,
                              void* d_out, int out_size)
{
    const float* x      = (const float*)d_in[0];
    const float* qkv_w  = (const float*)d_in[1];
    const float* proj_w = (const float*)d_in[2];
    const float* proj_b = (const float*)d_in[3];
    float*       out    = (float*)d_out;

    void *px3, *pw3, *po3, *ppw3;
    cudaGetSymbolAddress(&px3,  g_x3);
    cudaGetSymbolAddress(&pw3,  g_w3);
    cudaGetSymbolAddress(&po3,  g_o3);
    cudaGetSymbolAddress(&ppw3, g_pw3);

    static bool attr_set = false;
    if (!attr_set) {
        cudaFuncSetAttribute(mma_gemm<0>, cudaFuncAttributeMaxDynamicSharedMemorySize, GEMM_SMEM_BYTES);
        cudaFuncSetAttribute(mma_gemm<1>, cudaFuncAttributeMaxDynamicSharedMemorySize, GEMM_SMEM_BYTES);
        attr_set = true;
    }

    split3_kernel<0><<<(MROWS*DIM/4 + 255)/256, 256>>>(x,     (__nv_bfloat16*)px3,  MROWS*DIM/4);
    split3_kernel<1><<<(3*DIM*DIM/4 + 255)/256, 256>>>(qkv_w, (__nv_bfloat16*)pw3,  3*DIM*DIM/4);
    split3_kernel<1><<<(DIM*DIM/4   + 255)/256, 256>>>(proj_w,(__nv_bfloat16*)ppw3, DIM*DIM/4);

    // 1) QKV projection: M=4096 (256/CTA), N=3072 (128/CTA)
    mma_gemm<0><<<dim3(3*DIM/128, MROWS/256), 256, GEMM_SMEM_BYTES>>>(
        (const __nv_bfloat16*)px3, (const __nv_bfloat16*)pw3, nullptr, nullptr);

    // 2) flash attention (HMMA, split-3)
    attn_mma<<<dim3(SEQ/64, BS*NH), 128>>>();

    // 3) proj GEMM + bias: M=4096, N=1024 -> 128 CTAs (single wave)
    mma_gemm<1><<<dim3(DIM/128, MROWS/256), 256, GEMM_SMEM_BYTES>>>(
        (const __nv_bfloat16*)po3, (const __nv_bfloat16*)ppw3, proj_b, out);
}

// round 11
// speedup vs baseline: 1.0339x; 1.0339x over previous
#include <cuda_runtime.h>
#include <cuda_bf16.h>
#include <cstdint>

#define BS   2
#define SEQ  2048
#define DIM  1024
#define NH   16
#define HD   64
#define PREFIX 256
#define MROWS (BS*SEQ)
#define KT   (3*DIM)          // tripled K for bf16-split GEMM

// ------------------------- device scratch (no allocs) -----------------------
__device__ __nv_bfloat16 g_Qh[BS*NH*SEQ*HD];
__device__ __nv_bfloat16 g_Ql[BS*NH*SEQ*HD];
__device__ __nv_bfloat16 g_Kh[BS*NH*SEQ*HD];
__device__ __nv_bfloat16 g_Kl[BS*NH*SEQ*HD];
__device__ __nv_bfloat16 g_Vh[BS*NH*SEQ*HD];
__device__ __nv_bfloat16 g_Vl[BS*NH*SEQ*HD];
__device__ __nv_bfloat16 g_x3 [MROWS*KT];      // x split-3      (4096 x 3072)
__device__ __nv_bfloat16 g_w3 [3*DIM*KT];      // qkv_w split-3  (3072 x 3072)
__device__ __nv_bfloat16 g_o3 [MROWS*KT];      // attn out split (4096 x 3072)
__device__ __nv_bfloat16 g_pw3[DIM*KT];        // proj_w split-3 (1024 x 3072)

// ------------------------- portable PTX helpers (sm_80+) --------------------
__device__ __forceinline__ uint32_t smem_u32(const void* p) {
    uint32_t a;
    asm("{ .reg .u64 t; cvta.to.shared.u64 t, %1; cvt.u32.u64 %0, t; }" : "=r"(a) : "l"(p));
    return a;
}
__device__ __forceinline__ void cp16(uint32_t saddr, const void* g) {
    asm volatile("cp.async.cg.shared.global [%0], [%1], 16;" :: "r"(saddr), "l"(g));
}
#define CP_COMMIT()  asm volatile("cp.async.commit_group;" ::: "memory")
#define CP_WAIT(n)   asm volatile("cp.async.wait_group %0;" :: "n"(n) : "memory")

__device__ __forceinline__ void ldsm4(uint32_t* r, uint32_t addr) {
    asm volatile("ldmatrix.sync.aligned.m8n8.x4.shared.b16 {%0,%1,%2,%3}, [%4];"
                 : "=r"(r[0]), "=r"(r[1]), "=r"(r[2]), "=r"(r[3]) : "r"(addr));
}
__device__ __forceinline__ void ldsm4t(uint32_t* r, uint32_t addr) {
    asm volatile("ldmatrix.sync.aligned.m8n8.x4.trans.shared.b16 {%0,%1,%2,%3}, [%4];"
                 : "=r"(r[0]), "=r"(r[1]), "=r"(r[2]), "=r"(r[3]) : "r"(addr));
}
__device__ __forceinline__ void mma16816(float* c, const uint32_t* a, uint32_t b0, uint32_t b1) {
    asm volatile("mma.sync.aligned.m16n8k16.row.col.f32.bf16.bf16.f32 "
                 "{%0,%1,%2,%3}, {%4,%5,%6,%7}, {%8,%9}, {%0,%1,%2,%3};"
                 : "+f"(c[0]), "+f"(c[1]), "+f"(c[2]), "+f"(c[3])
                 : "r"(a[0]), "r"(a[1]), "r"(a[2]), "r"(a[3]), "r"(b0), "r"(b1));
}
__device__ __forceinline__ uint32_t pk2(__nv_bfloat16 lo, __nv_bfloat16 hi) {
    __nv_bfloat162 t; t.x = lo; t.y = hi;
    return *(uint32_t*)&t;
}

// ---------------------------------------------------------------------------
// split-3 conversion: fp32 -> bf16 triplets.
// MODE 0 (A side): [hi, lo, hi]   MODE 1 (B side): [hi, hi, lo]
// ---------------------------------------------------------------------------
template<int MODE>
__global__ __launch_bounds__(256) void split3_kernel(const float* __restrict__ src,
                                                     __nv_bfloat16* __restrict__ dst,
                                                     int n4)
{
    int i = blockIdx.x * blockDim.x + threadIdx.x;
    if (i >= n4) return;
    float4 v = ((const float4*)src)[i];
    float xs[4] = {v.x, v.y, v.z, v.w};
    __nv_bfloat16 t[12];
#pragma unroll
    for (int j = 0; j < 4; j++) {
        __nv_bfloat16 hi = __float2bfloat16(xs[j]);
        __nv_bfloat16 lo = __float2bfloat16(xs[j] - __bfloat162float(hi));
        t[3*j+0] = hi;
        t[3*j+1] = (MODE == 0) ? lo : hi;
        t[3*j+2] = (MODE == 0) ? hi : lo;
    }
    uint2* dp = (uint2*)(dst + (size_t)i * 12);
    const uint2* tp = (const uint2*)t;
    dp[0] = tp[0]; dp[1] = tp[1]; dp[2] = tp[2];
}

// ---------------------------------------------------------------------------
// HMMA bf16 GEMM v4: CTA 128x128, 4 warps in 2x2 grid, warp tile 64x64.
// 128-thread CTAs -> 2 independent CTAs/SM even at ~255 regs: sync stalls in
// one CTA are hidden by the other. smem intensity 10.7 MAC/B (reads+writes)
// -> crossbar 384 cyc/chunk < compute. 3-stage cp.async, 64B rows + XOR
// swizzle, 48KB static smem exactly.
// EPI 0: write Q/K/V as bf16 hi/lo pairs (Q * 0.125)   EPI 1: out = C + bias
// ---------------------------------------------------------------------------
template<int EPI>
__global__ __launch_bounds__(128) void mma_gemm(const __nv_bfloat16* __restrict__ A3,
                                                const __nv_bfloat16* __restrict__ B3,
                                                const float* __restrict__ bias,
                                                float* __restrict__ Cout)
{
    __shared__ __align__(16) __nv_bfloat16 sA[3][128*32];   // 8192 B / stage
    __shared__ __align__(16) __nv_bfloat16 sB[3][128*32];   // 8192 B / stage

    const int tid  = threadIdx.x;
    const int wid  = tid >> 5, lane = tid & 31;
    const int wm   = wid & 1,  wn   = wid >> 1;      // 2x2 warp grid
    const int bn   = blockIdx.x, bm = blockIdx.y;
    const int NCH  = KT / 32;                        // 96 chunks
    const uint32_t STB = 128 * 64;                   // stage bytes = 8192

    const char* Ab = (const char*)(A3 + (size_t)bm * 128 * KT);
    const char* Bb = (const char*)(B3 + (size_t)bn * 128 * KT);

    const uint32_t sA0 = smem_u32(&sA[0][0]);
    const uint32_t sB0 = smem_u32(&sB[0][0]);

    float acc[4][8][4];
#pragma unroll
    for (int i = 0; i < 4; i++)
#pragma unroll
        for (int j = 0; j < 8; j++)
#pragma unroll
            for (int k = 0; k < 4; k++) acc[i][j][k] = 0.f;

    // per chunk: A = 512 segs (4/thread), B = 512 segs (4/thread), 128 thr
#define LOAD_TILE(c, st)                                                           \
    {                                                                              \
        int koff = (c) * 64;                                                       \
        _Pragma("unroll")                                                          \
        for (int i = 0; i < 4; i++) {                                              \
            int idx = tid + i * 128;                                               \
            int row = idx >> 2, seg = idx & 3;                                     \
            int pseg = seg ^ ((row >> 1) & 3);                                     \
            uint32_t so = (uint32_t)((st) * STB + row * 64 + pseg * 16);           \
            cp16(sA0 + so, Ab + (size_t)row * (KT*2) + koff + seg * 16);           \
            cp16(sB0 + so, Bb + (size_t)row * (KT*2) + koff + seg * 16);           \
        }                                                                          \
    }

    LOAD_TILE(0, 0); CP_COMMIT();
    LOAD_TILE(1, 1); CP_COMMIT();

    const int lrow = lane & 15;
    const int lhalf = lane >> 4;                     // 0/1 -> +16B column

    int st = 0;                                      // stage of chunk c
    for (int c = 0; c < NCH; c++) {
        CP_WAIT(1);                                  // stage of chunk c complete
        __syncthreads();                             // everyone done with c-1 too

        if (c + 2 < NCH) {
            int st2 = (st + 2 >= 3) ? st - 1 : st + 2;
            LOAD_TILE(c + 2, st2);
        }
        CP_COMMIT();

        uint32_t abase = sA0 + st * STB;
        uint32_t bbase = sB0 + st * STB;
#pragma unroll
        for (int kg = 0; kg < 2; kg++) {
            uint32_t a[4][4], b[4][4];
            int lseg = kg * 2 + lhalf;
#pragma unroll
            for (int mt = 0; mt < 4; mt++) {
                int row = wm*64 + mt*16 + lrow;
                ldsm4(a[mt], abase + (uint32_t)(row * 64 + (lseg ^ ((row >> 1) & 3)) * 16));
            }
#pragma unroll
            for (int p = 0; p < 4; p++) {
                int row = wn*64 + p*16 + lrow;
                ldsm4(b[p], bbase + (uint32_t)(row * 64 + (lseg ^ ((row >> 1) & 3)) * 16));
            }
#pragma unroll
            for (int mt = 0; mt < 4; mt++)
#pragma unroll
                for (int nt = 0; nt < 8; nt++) {
                    int p = nt >> 1, q = nt & 1;
                    mma16816(acc[mt][nt], a[mt], b[p][q], b[p][q + 2]);
                }
        }
        st = (st + 1 >= 3) ? 0 : st + 1;
    }

#pragma unroll
    for (int mt = 0; mt < 4; mt++) {
#pragma unroll
        for (int nt = 0; nt < 8; nt++) {
            int m0 = bm * 128 + wm * 64 + mt * 16 + (lane >> 2);
            int n0 = bn * 128 + wn * 64 + nt * 8 + 2 * (lane & 3);
            float c0 = acc[mt][nt][0], c1 = acc[mt][nt][1];
            float c2 = acc[mt][nt][2], c3 = acc[mt][nt][3];
            if (EPI == 0) {
                int part = n0 >> 10;
                __nv_bfloat16 *dh = (part == 0) ? g_Qh : (part == 1) ? g_Kh : g_Vh;
                __nv_bfloat16 *dl = (part == 0) ? g_Ql : (part == 1) ? g_Kl : g_Vl;
                float scl = (part == 0) ? 0.125f : 1.0f;
                int head = (n0 & 1023) >> 6, d = n0 & 63;
#pragma unroll
                for (int rr = 0; rr < 2; rr++) {
                    int m = m0 + rr * 8;
                    int bi = m >> 11, s = m & (SEQ - 1);
                    float v0 = (rr ? c2 : c0) * scl, v1 = (rr ? c3 : c1) * scl;
                    __nv_bfloat16 h0 = __float2bfloat16(v0);
                    __nv_bfloat16 l0 = __float2bfloat16(v0 - __bfloat162float(h0));
                    __nv_bfloat16 h1 = __float2bfloat16(v1);
                    __nv_bfloat16 l1 = __float2bfloat16(v1 - __bfloat162float(h1));
                    size_t idx = (((size_t)(bi*NH + head))*SEQ + s)*HD + d;
                    *(uint32_t*)&dh[idx] = pk2(h0, h1);
                    *(uint32_t*)&dl[idx] = pk2(l0, l1);
                }
            } else {
                float2 bv = *(const float2*)&bias[n0];
                *(float2*)&Cout[(size_t)m0 * DIM + n0]       = make_float2(c0 + bv.x, c1 + bv.y);
                *(float2*)&Cout[(size_t)(m0 + 8) * DIM + n0] = make_float2(c2 + bv.x, c3 + bv.y);
            }
        }
    }
}

// ---------------------------------------------------------------------------
// HMMA flash attention (UNCHANGED — known-good).
// ---------------------------------------------------------------------------
__global__ __launch_bounds__(128) void attn_mma()
{
    __shared__ __align__(16) __nv_bfloat16 sQh[64*64];
    __shared__ __align__(16) __nv_bfloat16 sQl[64*64];
    __shared__ __align__(16) __nv_bfloat16 sKh[2][32*64];
    __shared__ __align__(16) __nv_bfloat16 sKl[2][32*64];
    __shared__ __align__(16) __nv_bfloat16 sVh[2][32*64];
    __shared__ __align__(16) __nv_bfloat16 sVl[2][32*64];

    const int qi  = blockIdx.x;
    const int bh  = blockIdx.y;
    const int b   = bh >> 4, h = bh & 15;
    const int tid = threadIdx.x, w = tid >> 5, lane = tid & 31;
    const int qbase = qi * 64;

    const size_t base = (size_t)bh * SEQ * HD;
    const uint32_t qh0 = smem_u32(sQh), ql0 = smem_u32(sQl);
    const uint32_t kh0 = smem_u32(sKh), kl0 = smem_u32(sKl);
    const uint32_t vh0 = smem_u32(sVh), vl0 = smem_u32(sVl);
    const uint32_t KVST = 32 * 128;

    for (int i = tid; i < 512; i += 128) {
        int r = i >> 3, seg = i & 7;
        int pseg = seg ^ (r & 7);
        const char* gq = (const char*)(g_Qh + base + (size_t)(qbase + r) * HD);
        const char* gl = (const char*)(g_Ql + base + (size_t)(qbase + r) * HD);
        cp16(qh0 + (uint32_t)(r * 128 + pseg * 16), gq + seg * 16);
        cp16(ql0 + (uint32_t)(r * 128 + pseg * 16), gl + seg * 16);
    }
    CP_COMMIT();

#define LOADKV(ch, st)                                                              \
    {                                                                               \
        int kb = (ch) * 32;                                                         \
        _Pragma("unroll")                                                           \
        for (int i = tid; i < 256; i += 128) {                                      \
            int r = i >> 3, seg = i & 7;                                            \
            int pseg = seg ^ (r & 7);                                               \
            size_t gidx = base + (size_t)(kb + r) * HD;                             \
            uint32_t so = (uint32_t)((st) * KVST + r * 128 + pseg * 16);            \
            cp16(kh0 + so, (const char*)(g_Kh + gidx) + seg * 16);                  \
            cp16(kl0 + so, (const char*)(g_Kl + gidx) + seg * 16);                  \
            cp16(vh0 + so, (const char*)(g_Vh + gidx) + seg * 16);                  \
            cp16(vl0 + so, (const char*)(g_Vl + gidx) + seg * 16);                  \
        }                                                                           \
    }

    const int nch = (qi < 4) ? 8 : 2 * (qi + 1);
    LOADKV(0, 0); CP_COMMIT();

    float o[8][4];
#pragma unroll
    for (int i = 0; i < 8; i++)
#pragma unroll
        for (int j = 0; j < 4; j++) o[i][j] = 0.f;
    float mi[2] = {-1e30f, -1e30f}, li[2] = {0.f, 0.f};

    const int lrow  = lane & 15;
    const int lhalf = lane >> 4;

    for (int ch = 0; ch < nch; ch++) {
        CP_WAIT(0);
        __syncthreads();
        if (ch + 1 < nch) { LOADKV(ch + 1, (ch + 1) & 1); }
        CP_COMMIT();

        const int kbase = ch * 32;
        const uint32_t kvoff = (uint32_t)((ch & 1) * KVST);

        float s[4][4];
#pragma unroll
        for (int nt = 0; nt < 4; nt++)
#pragma unroll
            for (int j = 0; j < 4; j++) s[nt][j] = 0.f;

#pragma unroll
        for (int kg = 0; kg < 4; kg++) {
            int lseg = kg * 2 + lhalf;
            uint32_t aH[4], aL[4], bH[2][4], bL[2][4];
            {
                int row = w*16 + lrow;
                uint32_t ao = (uint32_t)(row * 128 + (lseg ^ (row & 7)) * 16);
                ldsm4(aH, qh0 + ao);
                ldsm4(aL, ql0 + ao);
            }
#pragma unroll
            for (int p = 0; p < 2; p++) {
                int row = p*16 + lrow;
                uint32_t bo = kvoff + (uint32_t)(row * 128 + (lseg ^ (row & 7)) * 16);
                ldsm4(bH[p], kh0 + bo);
                ldsm4(bL[p], kl0 + bo);
            }
#pragma unroll
            for (int nt = 0; nt < 4; nt++) {
                int p = nt >> 1, q = nt & 1;
                mma16816(s[nt], aH, bH[p][q], bH[p][q+2]);
                mma16816(s[nt], aL, bH[p][q], bH[p][q+2]);
                mma16816(s[nt], aH, bL[p][q], bL[p][q+2]);
            }
        }

        if (kbase >= PREFIX && kbase + 31 > qbase) {
            int q0 = qbase + w*16 + (lane >> 2);
#pragma unroll
            for (int nt = 0; nt < 4; nt++) {
                int k0 = kbase + nt*8 + 2*(lane & 3);
                if (k0     > q0)     s[nt][0] = -1e30f;
                if (k0 + 1 > q0)     s[nt][1] = -1e30f;
                if (k0     > q0 + 8) s[nt][2] = -1e30f;
                if (k0 + 1 > q0 + 8) s[nt][3] = -1e30f;
            }
        }

#pragma unroll
        for (int rr = 0; rr < 2; rr++) {
            float mx = -1e30f;
#pragma unroll
            for (int nt = 0; nt < 4; nt++)
                mx = fmaxf(mx, fmaxf(s[nt][2*rr], s[nt][2*rr+1]));
            mx = fmaxf(mx, __shfl_xor_sync(0xffffffffu, mx, 1));
            mx = fmaxf(mx, __shfl_xor_sync(0xffffffffu, mx, 2));
            float mnew  = fmaxf(mi[rr], mx);
            float alpha = __expf(mi[rr] - mnew);
            float rs = 0.f;
#pragma unroll
            for (int nt = 0; nt < 4; nt++) {
                float p0 = __expf(s[nt][2*rr]   - mnew);
                float p1 = __expf(s[nt][2*rr+1] - mnew);
                s[nt][2*rr] = p0; s[nt][2*rr+1] = p1;
                rs += p0 + p1;
            }
            rs += __shfl_xor_sync(0xffffffffu, rs, 1);
            rs += __shfl_xor_sync(0xffffffffu, rs, 2);
            li[rr] = li[rr] * alpha + rs;
            mi[rr] = mnew;
#pragma unroll
            for (int dn = 0; dn < 8; dn++) {
                o[dn][2*rr] *= alpha; o[dn][2*rr+1] *= alpha;
            }
        }

#pragma unroll
        for (int kt = 0; kt < 2; kt++) {
            uint32_t pH[4], pL[4];
#pragma unroll
            for (int half = 0; half < 2; half++) {
                float* sv = s[2*kt + half];
                __nv_bfloat16 h0 = __float2bfloat16(sv[0]);
                __nv_bfloat16 h1 = __float2bfloat16(sv[1]);
                __nv_bfloat16 h2 = __float2bfloat16(sv[2]);
                __nv_bfloat16 h3 = __float2bfloat16(sv[3]);
                __nv_bfloat16 l0 = __float2bfloat16(sv[0] - __bfloat162float(h0));
                __nv_bfloat16 l1 = __float2bfloat16(sv[1] - __bfloat162float(h1));
                __nv_bfloat16 l2 = __float2bfloat16(sv[2] - __bfloat162float(h2));
                __nv_bfloat16 l3 = __float2bfloat16(sv[3] - __bfloat162float(h3));
                pH[half*2+0] = pk2(h0, h1); pH[half*2+1] = pk2(h2, h3);
                pL[half*2+0] = pk2(l0, l1); pL[half*2+1] = pk2(l2, l3);
            }
#pragma unroll
            for (int p4 = 0; p4 < 4; p4++) {
                int row = kt*16 + lrow;
                int lseg = p4*2 + lhalf;
                uint32_t vo = kvoff + (uint32_t)(row * 128 + (lseg ^ (row & 7)) * 16);
                uint32_t vH[4], vL[4];
                ldsm4t(vH, vh0 + vo);
                ldsm4t(vL, vl0 + vo);
                mma16816(o[2*p4],   pH, vH[0], vH[1]);
                mma16816(o[2*p4],   pL, vH[0], vH[1]);
                mma16816(o[2*p4],   pH, vL[0], vL[1]);
                mma16816(o[2*p4+1], pH, vH[2], vH[3]);
                mma16816(o[2*p4+1], pL, vH[2], vH[3]);
                mma16816(o[2*p4+1], pH, vL[2], vL[3]);
            }
        }
    }

#pragma unroll
    for (int dn = 0; dn < 8; dn++) {
        int d0 = dn*8 + 2*(lane & 3);
#pragma unroll
        for (int rr = 0; rr < 2; rr++) {
            int row = qbase + w*16 + (lane >> 2) + rr*8;
            float inv = 1.0f / li[rr];
            float v0 = o[dn][2*rr]   * inv;
            float v1 = o[dn][2*rr+1] * inv;
            __nv_bfloat16 h0 = __float2bfloat16(v0);
            __nv_bfloat16 l0 = __float2bfloat16(v0 - __bfloat162float(h0));
            __nv_bfloat16 h1 = __float2bfloat16(v1);
            __nv_bfloat16 l1 = __float2bfloat16(v1 - __bfloat162float(h1));
            size_t off = (size_t)(b*SEQ + row) * KT + (size_t)3 * (h*HD + d0);
            *(uint32_t*)&g_o3[off]     = pk2(h0, l0);
            *(uint32_t*)&g_o3[off + 2] = pk2(h0, h1);
            *(uint32_t*)&g_o3[off + 4] = pk2(l1, h1);
        }
    }
}

// ---------------------------------------------------------------------------
extern "C" void kernel_launch(void* const* d_in, const int* in_sizes, int n_in,
                              void* d_out, int out_size)
{
    const float* x      = (const float*)d_in[0];
    const float* qkv_w  = (const float*)d_in[1];
    const float* proj_w = (const float*)d_in[2];
    const float* proj_b = (const float*)d_in[3];
    float*       out    = (float*)d_out;

    void *px3, *pw3, *po3, *ppw3;
    cudaGetSymbolAddress(&px3,  g_x3);
    cudaGetSymbolAddress(&pw3,  g_w3);
    cudaGetSymbolAddress(&po3,  g_o3);
    cudaGetSymbolAddress(&ppw3, g_pw3);

    split3_kernel<0><<<(MROWS*DIM/4 + 255)/256, 256>>>(x,     (__nv_bfloat16*)px3,  MROWS*DIM/4);
    split3_kernel<1><<<(3*DIM*DIM/4 + 255)/256, 256>>>(qkv_w, (__nv_bfloat16*)pw3,  3*DIM*DIM/4);
    split3_kernel<1><<<(DIM*DIM/4   + 255)/256, 256>>>(proj_w,(__nv_bfloat16*)ppw3, DIM*DIM/4);

    // 1) QKV projection: M=4096, N=3072, CTA 128x128, 128 threads
    mma_gemm<0><<<dim3(3*DIM/128, MROWS/128), 128>>>(
        (const __nv_bfloat16*)px3, (const __nv_bfloat16*)pw3, nullptr, nullptr);

    // 2) flash attention (HMMA, split-3)
    attn_mma<<<dim3(SEQ/64, BS*NH), 128>>>();

    // 3) proj GEMM + bias: M=4096, N=1024
    mma_gemm<1><<<dim3(DIM/128, MROWS/128), 128>>>(
        (const __nv_bfloat16*)po3, (const __nv_bfloat16*)ppw3, proj_b, out);
}

// round 12
// speedup vs baseline: 1.5301x; 1.4800x over previous
#include <cuda_runtime.h>
#include <cuda_fp16.h>
#include <cstdint>

#define BS   2
#define SEQ  2048
#define DIM  1024
#define NH   16
#define HD   64
#define PREFIX 256
#define MROWS (BS*SEQ)
#define KT   (2*DIM)          // DOUBLED K for fp16 split-2 GEMM

// ------------------------- device scratch (no allocs) -----------------------
__device__ __half g_Qh[BS*NH*SEQ*HD];
__device__ __half g_Ql[BS*NH*SEQ*HD];
__device__ __half g_Kh[BS*NH*SEQ*HD];
__device__ __half g_Vh[BS*NH*SEQ*HD];
__device__ __half g_x2 [MROWS*KT];      // x split-2      (4096 x 2048)
__device__ __half g_w2 [3*DIM*KT];      // qkv_w dup-hi   (3072 x 2048)
__device__ __half g_o2 [MROWS*KT];      // attn out split (4096 x 2048)
__device__ __half g_pw2[DIM*KT];        // proj_w dup-hi  (1024 x 2048)

// ------------------------- portable PTX helpers (sm_80+) --------------------
__device__ __forceinline__ uint32_t smem_u32(const void* p) {
    uint32_t a;
    asm("{ .reg .u64 t; cvta.to.shared.u64 t, %1; cvt.u32.u64 %0, t; }" : "=r"(a) : "l"(p));
    return a;
}
__device__ __forceinline__ void cp16(uint32_t saddr, const void* g) {
    asm volatile("cp.async.cg.shared.global [%0], [%1], 16;" :: "r"(saddr), "l"(g));
}
#define CP_COMMIT()  asm volatile("cp.async.commit_group;" ::: "memory")
#define CP_WAIT(n)   asm volatile("cp.async.wait_group %0;" :: "n"(n) : "memory")

__device__ __forceinline__ void ldsm4(uint32_t* r, uint32_t addr) {
    asm volatile("ldmatrix.sync.aligned.m8n8.x4.shared.b16 {%0,%1,%2,%3}, [%4];"
                 : "=r"(r[0]), "=r"(r[1]), "=r"(r[2]), "=r"(r[3]) : "r"(addr));
}
__device__ __forceinline__ void ldsm4t(uint32_t* r, uint32_t addr) {
    asm volatile("ldmatrix.sync.aligned.m8n8.x4.trans.shared.b16 {%0,%1,%2,%3}, [%4];"
                 : "=r"(r[0]), "=r"(r[1]), "=r"(r[2]), "=r"(r[3]) : "r"(addr));
}
__device__ __forceinline__ void mma16816(float* c, const uint32_t* a, uint32_t b0, uint32_t b1) {
    asm volatile("mma.sync.aligned.m16n8k16.row.col.f32.f16.f16.f32 "
                 "{%0,%1,%2,%3}, {%4,%5,%6,%7}, {%8,%9}, {%0,%1,%2,%3};"
                 : "+f"(c[0]), "+f"(c[1]), "+f"(c[2]), "+f"(c[3])
                 : "r"(a[0]), "r"(a[1]), "r"(a[2]), "r"(a[3]), "r"(b0), "r"(b1));
}
__device__ __forceinline__ uint32_t pkh2(__half a, __half b) {
    __half2 t; t.x = a; t.y = b;
    return *(uint32_t*)&t;
}

// ---------------------------------------------------------------------------
// split-2 conversion: fp32 -> fp16 pairs.
// MODE 0 (A side): [hi, lo]   MODE 1 (B side): [hi, hi]
// A2 . B2 over 2K = Ah*Bh + Al*Bh = A*Bh  (error A*Bl ~ 1.6e-4 rms)
// ---------------------------------------------------------------------------
template<int MODE>
__global__ __launch_bounds__(256) void split2_kernel(const float* __restrict__ src,
                                                     __half* __restrict__ dst,
                                                     int n4)
{
    int i = blockIdx.x * blockDim.x + threadIdx.x;
    if (i >= n4) return;
    float4 v = ((const float4*)src)[i];
    float xs[4] = {v.x, v.y, v.z, v.w};
    __half t[8];
#pragma unroll
    for (int j = 0; j < 4; j++) {
        __half hi = __float2half_rn(xs[j]);
        __half lo = __float2half_rn(xs[j] - __half2float(hi));
        t[2*j+0] = hi;
        t[2*j+1] = (MODE == 0) ? lo : hi;
    }
    *(uint4*)(dst + (size_t)i * 8) = *(const uint4*)t;
}

// ---------------------------------------------------------------------------
// HMMA fp16 GEMM: CTA 128x128, 8 warps (2x4), warp tile 64x32 (round-8 cfg —
// best measured). 3-stage cp.async, 64B rows + XOR swizzle, 48KB static.
// K' = 2048 -> 64 chunks (2/3 the mma instructions of bf16 split-3).
// EPI 0: Q -> hi+lo arrays (x0.125), K/V -> hi only.  EPI 1: out = C + bias.
// ---------------------------------------------------------------------------
template<int EPI>
__global__ __launch_bounds__(256, 2) void mma_gemm(const __half* __restrict__ A2,
                                                   const __half* __restrict__ B2,
                                                   const float* __restrict__ bias,
                                                   float* __restrict__ Cout)
{
    __shared__ __align__(16) __half sA[3][128*32];   // 8192 B / stage
    __shared__ __align__(16) __half sB[3][128*32];

    const int tid  = threadIdx.x;
    const int wid  = tid >> 5, lane = tid & 31;
    const int wm   = wid & 1,  wn   = wid >> 1;      // 2x4 warp grid
    const int bn   = blockIdx.x, bm = blockIdx.y;
    const int NCH  = KT / 32;                        // 64 chunks
    const uint32_t STB = 128 * 64;                   // stage bytes = 8192

    const char* Ab = (const char*)(A2 + (size_t)bm * 128 * KT);
    const char* Bb = (const char*)(B2 + (size_t)bn * 128 * KT);

    const uint32_t sA0 = smem_u32(&sA[0][0]);
    const uint32_t sB0 = smem_u32(&sB[0][0]);

    float acc[4][4][4];
#pragma unroll
    for (int i = 0; i < 4; i++)
#pragma unroll
        for (int j = 0; j < 4; j++)
#pragma unroll
            for (int k = 0; k < 4; k++) acc[i][j][k] = 0.f;

#define LOAD_TILE(c, st)                                                           \
    {                                                                              \
        int koff = (c) * 64;                                                       \
        _Pragma("unroll")                                                          \
        for (int i = 0; i < 2; i++) {                                              \
            int idx = tid + i * 256;                                               \
            int row = idx >> 2, seg = idx & 3;                                     \
            int pseg = seg ^ ((row >> 1) & 3);                                     \
            uint32_t so = (uint32_t)((st) * STB + row * 64 + pseg * 16);           \
            cp16(sA0 + so, Ab + (size_t)row * (KT*2) + koff + seg * 16);           \
            cp16(sB0 + so, Bb + (size_t)row * (KT*2) + koff + seg * 16);           \
        }                                                                          \
    }

    LOAD_TILE(0, 0); CP_COMMIT();
    LOAD_TILE(1, 1); CP_COMMIT();

    const int lrow = lane & 15;
    const int lhalf = lane >> 4;                     // 0/1 -> +16B column

    int st = 0;
    for (int c = 0; c < NCH; c++) {
        CP_WAIT(1);
        __syncthreads();

        if (c + 2 < NCH) {
            int st2 = (st + 2 >= 3) ? st - 1 : st + 2;
            LOAD_TILE(c + 2, st2);
        }
        CP_COMMIT();

        uint32_t abase = sA0 + st * STB;
        uint32_t bbase = sB0 + st * STB;
#pragma unroll
        for (int kg = 0; kg < 2; kg++) {
            uint32_t a[4][4], b[2][4];
            int lseg = kg * 2 + lhalf;
#pragma unroll
            for (int mt = 0; mt < 4; mt++) {
                int row = wm*64 + mt*16 + lrow;
                ldsm4(a[mt], abase + (uint32_t)(row * 64 + (lseg ^ ((row >> 1) & 3)) * 16));
            }
#pragma unroll
            for (int p = 0; p < 2; p++) {
                int row = wn*32 + p*16 + lrow;
                ldsm4(b[p], bbase + (uint32_t)(row * 64 + (lseg ^ ((row >> 1) & 3)) * 16));
            }
#pragma unroll
            for (int mt = 0; mt < 4; mt++)
#pragma unroll
                for (int nt = 0; nt < 4; nt++) {
                    int p = nt >> 1, q = nt & 1;
                    mma16816(acc[mt][nt], a[mt], b[p][q], b[p][q + 2]);
                }
        }
        st = (st + 1 >= 3) ? 0 : st + 1;
    }

#pragma unroll
    for (int mt = 0; mt < 4; mt++) {
#pragma unroll
        for (int nt = 0; nt < 4; nt++) {
            int m0 = bm * 128 + wm * 64 + mt * 16 + (lane >> 2);
            int n0 = bn * 128 + wn * 32 + nt * 8 + 2 * (lane & 3);
            float c0 = acc[mt][nt][0], c1 = acc[mt][nt][1];
            float c2 = acc[mt][nt][2], c3 = acc[mt][nt][3];
            if (EPI == 0) {
                int part = n0 >> 10;
                __half* dh = (part == 0) ? g_Qh : (part == 1) ? g_Kh : g_Vh;
                float scl = (part == 0) ? 0.125f : 1.0f;
                int head = (n0 & 1023) >> 6, d = n0 & 63;
#pragma unroll
                for (int rr = 0; rr < 2; rr++) {
                    int m = m0 + rr * 8;
                    int bi = m >> 11, s = m & (SEQ - 1);
                    float v0 = (rr ? c2 : c0) * scl, v1 = (rr ? c3 : c1) * scl;
                    __half h0 = __float2half_rn(v0);
                    __half h1 = __float2half_rn(v1);
                    size_t idx = (((size_t)(bi*NH + head))*SEQ + s)*HD + d;
                    *(uint32_t*)&dh[idx] = pkh2(h0, h1);
                    if (part == 0) {
                        __half l0 = __float2half_rn(v0 - __half2float(h0));
                        __half l1 = __float2half_rn(v1 - __half2float(h1));
                        *(uint32_t*)&g_Ql[idx] = pkh2(l0, l1);
                    }
                }
            } else {
                float2 bv = *(const float2*)&bias[n0];
                *(float2*)&Cout[(size_t)m0 * DIM + n0]       = make_float2(c0 + bv.x, c1 + bv.y);
                *(float2*)&Cout[(size_t)(m0 + 8) * DIM + n0] = make_float2(c2 + bv.x, c3 + bv.y);
            }
        }
    }
}

// ---------------------------------------------------------------------------
// HMMA fp16 flash attention, split-2: S = (Qh+Ql).Kh (2 passes),
// O += (Ph+Pl).Vh (2 passes). K/V hi arrays only -> KV traffic halved.
// CTA = 64 queries x one (b,h), 4 warps, 2-stage cp.async KV, 32KB smem.
// qi remapped longest-first to fix wave-tail imbalance.
// Mask: allowed(q,k) = (k <= q) || (k < 256). Q pre-scaled by 1/8.
// ---------------------------------------------------------------------------
__global__ __launch_bounds__(128) void attn_mma()
{
    __shared__ __align__(16) __half sQh[64*64];       // 8192 B
    __shared__ __align__(16) __half sQl[64*64];       // 8192 B
    __shared__ __align__(16) __half sKh[2][32*64];    // 8192 B
    __shared__ __align__(16) __half sVh[2][32*64];    // 8192 B => 32 KB

    const int qi  = (SEQ/64 - 1) - blockIdx.x;        // longest first
    const int bh  = blockIdx.y;
    const int b   = bh >> 4, h = bh & 15;
    const int tid = threadIdx.x, w = tid >> 5, lane = tid & 31;
    const int qbase = qi * 64;

    const size_t base = (size_t)bh * SEQ * HD;
    const uint32_t qh0 = smem_u32(sQh), ql0 = smem_u32(sQl);
    const uint32_t kh0 = smem_u32(sKh), vh0 = smem_u32(sVh);
    const uint32_t KVST = 32 * 128;                   // 4096 B per stage

    // Q tile via cp.async (64 rows x 128B, swizzled)
    for (int i = tid; i < 512; i += 128) {
        int r = i >> 3, seg = i & 7;
        int pseg = seg ^ (r & 7);
        const char* gq = (const char*)(g_Qh + base + (size_t)(qbase + r) * HD);
        const char* gl = (const char*)(g_Ql + base + (size_t)(qbase + r) * HD);
        cp16(qh0 + (uint32_t)(r * 128 + pseg * 16), gq + seg * 16);
        cp16(ql0 + (uint32_t)(r * 128 + pseg * 16), gl + seg * 16);
    }
    CP_COMMIT();

#define LOADKV(ch, st)                                                              \
    {                                                                               \
        int kb = (ch) * 32;                                                         \
        _Pragma("unroll")                                                           \
        for (int i = tid; i < 256; i += 128) {                                      \
            int r = i >> 3, seg = i & 7;                                            \
            int pseg = seg ^ (r & 7);                                               \
            size_t gidx = base + (size_t)(kb + r) * HD;                             \
            uint32_t so = (uint32_t)((st) * KVST + r * 128 + pseg * 16);            \
            cp16(kh0 + so, (const char*)(g_Kh + gidx) + seg * 16);                  \
            cp16(vh0 + so, (const char*)(g_Vh + gidx) + seg * 16);                  \
        }                                                                           \
    }

    const int nch = (qi < 4) ? 8 : 2 * (qi + 1);
    LOADKV(0, 0); CP_COMMIT();

    float o[8][4];
#pragma unroll
    for (int i = 0; i < 8; i++)
#pragma unroll
        for (int j = 0; j < 4; j++) o[i][j] = 0.f;
    float mi[2] = {-1e30f, -1e30f}, li[2] = {0.f, 0.f};

    const int lrow  = lane & 15;
    const int lhalf = lane >> 4;

    for (int ch = 0; ch < nch; ch++) {
        CP_WAIT(0);
        __syncthreads();
        if (ch + 1 < nch) { LOADKV(ch + 1, (ch + 1) & 1); }
        CP_COMMIT();

        const int kbase = ch * 32;
        const uint32_t kvoff = (uint32_t)((ch & 1) * KVST);

        // ---- S = (Qh+Ql) Kh^T : 2 passes ----
        float s[4][4];
#pragma unroll
        for (int nt = 0; nt < 4; nt++)
#pragma unroll
            for (int j = 0; j < 4; j++) s[nt][j] = 0.f;

#pragma unroll
        for (int kg = 0; kg < 4; kg++) {
            int lseg = kg * 2 + lhalf;
            uint32_t aH[4], aL[4], bH[2][4];
            {
                int row = w*16 + lrow;
                uint32_t ao = (uint32_t)(row * 128 + (lseg ^ (row & 7)) * 16);
                ldsm4(aH, qh0 + ao);
                ldsm4(aL, ql0 + ao);
            }
#pragma unroll
            for (int p = 0; p < 2; p++) {
                int row = p*16 + lrow;
                ldsm4(bH[p], kh0 + kvoff + (uint32_t)(row * 128 + (lseg ^ (row & 7)) * 16));
            }
#pragma unroll
            for (int nt = 0; nt < 4; nt++) {
                int p = nt >> 1, q = nt & 1;
                mma16816(s[nt], aH, bH[p][q], bH[p][q+2]);
                mma16816(s[nt], aL, bH[p][q], bH[p][q+2]);
            }
        }

        // ---- causal mask (only near-diagonal chunks outside prefix) ----
        if (kbase >= PREFIX && kbase + 31 > qbase) {
            int q0 = qbase + w*16 + (lane >> 2);
#pragma unroll
            for (int nt = 0; nt < 4; nt++) {
                int k0 = kbase + nt*8 + 2*(lane & 3);
                if (k0     > q0)     s[nt][0] = -1e30f;
                if (k0 + 1 > q0)     s[nt][1] = -1e30f;
                if (k0     > q0 + 8) s[nt][2] = -1e30f;
                if (k0 + 1 > q0 + 8) s[nt][3] = -1e30f;
            }
        }

        // ---- online softmax (rows r and r+8), quad shfl reductions ----
#pragma unroll
        for (int rr = 0; rr < 2; rr++) {
            float mx = -1e30f;
#pragma unroll
            for (int nt = 0; nt < 4; nt++)
                mx = fmaxf(mx, fmaxf(s[nt][2*rr], s[nt][2*rr+1]));
            mx = fmaxf(mx, __shfl_xor_sync(0xffffffffu, mx, 1));
            mx = fmaxf(mx, __shfl_xor_sync(0xffffffffu, mx, 2));
            float mnew  = fmaxf(mi[rr], mx);
            float alpha = __expf(mi[rr] - mnew);
            float rs = 0.f;
#pragma unroll
            for (int nt = 0; nt < 4; nt++) {
                float p0 = __expf(s[nt][2*rr]   - mnew);
                float p1 = __expf(s[nt][2*rr+1] - mnew);
                s[nt][2*rr] = p0; s[nt][2*rr+1] = p1;
                rs += p0 + p1;
            }
            rs += __shfl_xor_sync(0xffffffffu, rs, 1);
            rs += __shfl_xor_sync(0xffffffffu, rs, 2);
            li[rr] = li[rr] * alpha + rs;
            mi[rr] = mnew;
#pragma unroll
            for (int dn = 0; dn < 8; dn++) {
                o[dn][2*rr] *= alpha; o[dn][2*rr+1] *= alpha;
            }
        }

        // ---- O += (Ph+Pl) Vh : 2 passes; P frags built in registers ----
#pragma unroll
        for (int kt = 0; kt < 2; kt++) {
            uint32_t pH[4], pL[4];
#pragma unroll
            for (int half = 0; half < 2; half++) {
                float* sv = s[2*kt + half];
                __half h0 = __float2half_rn(sv[0]);
                __half h1 = __float2half_rn(sv[1]);
                __half h2 = __float2half_rn(sv[2]);
                __half h3 = __float2half_rn(sv[3]);
                __half l0 = __float2half_rn(sv[0] - __half2float(h0));
                __half l1 = __float2half_rn(sv[1] - __half2float(h1));
                __half l2 = __float2half_rn(sv[2] - __half2float(h2));
                __half l3 = __float2half_rn(sv[3] - __half2float(h3));
                pH[half*2+0] = pkh2(h0, h1); pH[half*2+1] = pkh2(h2, h3);
                pL[half*2+0] = pkh2(l0, l1); pL[half*2+1] = pkh2(l2, l3);
            }
#pragma unroll
            for (int p4 = 0; p4 < 4; p4++) {
                int row = kt*16 + lrow;
                int lseg = p4*2 + lhalf;
                uint32_t vo = kvoff + (uint32_t)(row * 128 + (lseg ^ (row & 7)) * 16);
                uint32_t vH[4];
                ldsm4t(vH, vh0 + vo);
                mma16816(o[2*p4],   pH, vH[0], vH[1]);
                mma16816(o[2*p4],   pL, vH[0], vH[1]);
                mma16816(o[2*p4+1], pH, vH[2], vH[3]);
                mma16816(o[2*p4+1], pL, vH[2], vH[3]);
            }
        }
    }

    // ---- epilogue: normalize, split-2, write g_o2 pairs [hi,lo] ----
#pragma unroll
    for (int dn = 0; dn < 8; dn++) {
        int d0 = dn*8 + 2*(lane & 3);
#pragma unroll
        for (int rr = 0; rr < 2; rr++) {
            int row = qbase + w*16 + (lane >> 2) + rr*8;
            float inv = 1.0f / li[rr];
            float v0 = o[dn][2*rr]   * inv;
            float v1 = o[dn][2*rr+1] * inv;
            __half h0 = __float2half_rn(v0);
            __half l0 = __float2half_rn(v0 - __half2float(h0));
            __half h1 = __float2half_rn(v1);
            __half l1 = __float2half_rn(v1 - __half2float(h1));
            size_t off = (size_t)(b*SEQ + row) * KT + (size_t)2 * (h*HD + d0);
            *(uint32_t*)&g_o2[off]     = pkh2(h0, l0);
            *(uint32_t*)&g_o2[off + 2] = pkh2(h1, l1);
        }
    }
}

// ---------------------------------------------------------------------------
extern "C" void kernel_launch(void* const* d_in, const int* in_sizes, int n_in,
                              void* d_out, int out_size)
{
    const float* x      = (const float*)d_in[0];
    const float* qkv_w  = (const float*)d_in[1];
    const float* proj_w = (const float*)d_in[2];
    const float* proj_b = (const float*)d_in[3];
    float*       out    = (float*)d_out;

    void *px2, *pw2, *po2, *ppw2;
    cudaGetSymbolAddress(&px2,  g_x2);
    cudaGetSymbolAddress(&pw2,  g_w2);
    cudaGetSymbolAddress(&po2,  g_o2);
    cudaGetSymbolAddress(&ppw2, g_pw2);

    split2_kernel<0><<<(MROWS*DIM/4 + 255)/256, 256>>>(x,     (__half*)px2,  MROWS*DIM/4);
    split2_kernel<1><<<(3*DIM*DIM/4 + 255)/256, 256>>>(qkv_w, (__half*)pw2,  3*DIM*DIM/4);
    split2_kernel<1><<<(DIM*DIM/4   + 255)/256, 256>>>(proj_w,(__half*)ppw2, DIM*DIM/4);

    // 1) QKV projection (HMMA fp16 split-2): M=4096, N=3072, K'=2048
    mma_gemm<0><<<dim3(3*DIM/128, MROWS/128), 256>>>(
        (const __half*)px2, (const __half*)pw2, nullptr, nullptr);

    // 2) flash attention (HMMA fp16 split-2)
    attn_mma<<<dim3(SEQ/64, BS*NH), 128>>>();

    // 3) proj GEMM + bias: M=4096, N=1024, K'=2048
    mma_gemm<1><<<dim3(DIM/128, MROWS/128), 256>>>(
        (const __half*)po2, (const __half*)ppw2, proj_b, out);
}

// round 13
// speedup vs baseline: 2.1193x; 1.3851x over previous
#include <cuda_runtime.h>
#include <cuda_fp16.h>
#include <cstdint>

#define BS   2
#define SEQ  2048
#define DIM  1024
#define NH   16
#define HD   64
#define PREFIX 256
#define MROWS (BS*SEQ)
#define KT   DIM              // plain fp16 GEMM K (no split duplication)

// ------------------------- device scratch (no allocs) -----------------------
__device__ __half g_Qh[BS*NH*SEQ*HD];
__device__ __half g_Ql[BS*NH*SEQ*HD];
__device__ __half g_Kh[BS*NH*SEQ*HD];
__device__ __half g_Vh[BS*NH*SEQ*HD];
__device__ __half g_x16 [MROWS*DIM];     // x fp16        (4096 x 1024)
__device__ __half g_w16 [3*DIM*DIM];     // qkv_w fp16    (3072 x 1024)
__device__ __half g_o16 [MROWS*DIM];     // attn out fp16 (4096 x 1024)
__device__ __half g_pw16[DIM*DIM];       // proj_w fp16   (1024 x 1024)

// ------------------------- portable PTX helpers (sm_80+) --------------------
__device__ __forceinline__ uint32_t smem_u32(const void* p) {
    uint32_t a;
    asm("{ .reg .u64 t; cvta.to.shared.u64 t, %1; cvt.u32.u64 %0, t; }" : "=r"(a) : "l"(p));
    return a;
}
__device__ __forceinline__ void cp16(uint32_t saddr, const void* g) {
    asm volatile("cp.async.cg.shared.global [%0], [%1], 16;" :: "r"(saddr), "l"(g));
}
#define CP_COMMIT()  asm volatile("cp.async.commit_group;" ::: "memory")
#define CP_WAIT(n)   asm volatile("cp.async.wait_group %0;" :: "n"(n) : "memory")

__device__ __forceinline__ void ldsm4(uint32_t* r, uint32_t addr) {
    asm volatile("ldmatrix.sync.aligned.m8n8.x4.shared.b16 {%0,%1,%2,%3}, [%4];"
                 : "=r"(r[0]), "=r"(r[1]), "=r"(r[2]), "=r"(r[3]) : "r"(addr));
}
__device__ __forceinline__ void ldsm4t(uint32_t* r, uint32_t addr) {
    asm volatile("ldmatrix.sync.aligned.m8n8.x4.trans.shared.b16 {%0,%1,%2,%3}, [%4];"
                 : "=r"(r[0]), "=r"(r[1]), "=r"(r[2]), "=r"(r[3]) : "r"(addr));
}
__device__ __forceinline__ void mma16816(float* c, const uint32_t* a, uint32_t b0, uint32_t b1) {
    asm volatile("mma.sync.aligned.m16n8k16.row.col.f32.f16.f16.f32 "
                 "{%0,%1,%2,%3}, {%4,%5,%6,%7}, {%8,%9}, {%0,%1,%2,%3};"
                 : "+f"(c[0]), "+f"(c[1]), "+f"(c[2]), "+f"(c[3])
                 : "r"(a[0]), "r"(a[1]), "r"(a[2]), "r"(a[3]), "r"(b0), "r"(b1));
}
__device__ __forceinline__ uint32_t pkh2(__half a, __half b) {
    __half2 t; t.x = a; t.y = b;
    return *(uint32_t*)&t;
}

// ---------------------------------------------------------------------------
// fp32 -> fp16 conversion (round to nearest)
// ---------------------------------------------------------------------------
__global__ __launch_bounds__(256) void cvt16_kernel(const float* __restrict__ src,
                                                    __half* __restrict__ dst,
                                                    int n4)
{
    int i = blockIdx.x * blockDim.x + threadIdx.x;
    if (i >= n4) return;
    float4 v = ((const float4*)src)[i];
    __half t[4];
    t[0] = __float2half_rn(v.x); t[1] = __float2half_rn(v.y);
    t[2] = __float2half_rn(v.z); t[3] = __float2half_rn(v.w);
    *(uint2*)(dst + (size_t)i * 4) = *(const uint2*)t;
}

// ---------------------------------------------------------------------------
// HMMA fp16 GEMM: CTA 128x128, 8 warps (2x4), warp tile 64x32. K=1024, 32
// chunks. 3-stage cp.async, 64B rows + XOR swizzle, 48KB static smem.
// EPI 0: Q -> hi+lo arrays (x0.125), K/V -> hi only.  EPI 1: out = C + bias.
// ---------------------------------------------------------------------------
template<int EPI>
__global__ __launch_bounds__(256, 2) void mma_gemm(const __half* __restrict__ A2,
                                                   const __half* __restrict__ B2,
                                                   const float* __restrict__ bias,
                                                   float* __restrict__ Cout)
{
    __shared__ __align__(16) __half sA[3][128*32];   // 8192 B / stage
    __shared__ __align__(16) __half sB[3][128*32];

    const int tid  = threadIdx.x;
    const int wid  = tid >> 5, lane = tid & 31;
    const int wm   = wid & 1,  wn   = wid >> 1;      // 2x4 warp grid
    const int bn   = blockIdx.x, bm = blockIdx.y;
    const int NCH  = KT / 32;                        // 32 chunks
    const uint32_t STB = 128 * 64;                   // stage bytes = 8192

    const char* Ab = (const char*)(A2 + (size_t)bm * 128 * KT);
    const char* Bb = (const char*)(B2 + (size_t)bn * 128 * KT);

    const uint32_t sA0 = smem_u32(&sA[0][0]);
    const uint32_t sB0 = smem_u32(&sB[0][0]);

    float acc[4][4][4];
#pragma unroll
    for (int i = 0; i < 4; i++)
#pragma unroll
        for (int j = 0; j < 4; j++)
#pragma unroll
            for (int k = 0; k < 4; k++) acc[i][j][k] = 0.f;

#define LOAD_TILE(c, st)                                                           \
    {                                                                              \
        int koff = (c) * 64;                                                       \
        _Pragma("unroll")                                                          \
        for (int i = 0; i < 2; i++) {                                              \
            int idx = tid + i * 256;                                               \
            int row = idx >> 2, seg = idx & 3;                                     \
            int pseg = seg ^ ((row >> 1) & 3);                                     \
            uint32_t so = (uint32_t)((st) * STB + row * 64 + pseg * 16);           \
            cp16(sA0 + so, Ab + (size_t)row * (KT*2) + koff + seg * 16);           \
            cp16(sB0 + so, Bb + (size_t)row * (KT*2) + koff + seg * 16);           \
        }                                                                          \
    }

    LOAD_TILE(0, 0); CP_COMMIT();
    LOAD_TILE(1, 1); CP_COMMIT();

    const int lrow = lane & 15;
    const int lhalf = lane >> 4;                     // 0/1 -> +16B column

    int st = 0;
    for (int c = 0; c < NCH; c++) {
        CP_WAIT(1);
        __syncthreads();

        if (c + 2 < NCH) {
            int st2 = (st + 2 >= 3) ? st - 1 : st + 2;
            LOAD_TILE(c + 2, st2);
        }
        CP_COMMIT();

        uint32_t abase = sA0 + st * STB;
        uint32_t bbase = sB0 + st * STB;
#pragma unroll
        for (int kg = 0; kg < 2; kg++) {
            uint32_t a[4][4], b[2][4];
            int lseg = kg * 2 + lhalf;
#pragma unroll
            for (int mt = 0; mt < 4; mt++) {
                int row = wm*64 + mt*16 + lrow;
                ldsm4(a[mt], abase + (uint32_t)(row * 64 + (lseg ^ ((row >> 1) & 3)) * 16));
            }
#pragma unroll
            for (int p = 0; p < 2; p++) {
                int row = wn*32 + p*16 + lrow;
                ldsm4(b[p], bbase + (uint32_t)(row * 64 + (lseg ^ ((row >> 1) & 3)) * 16));
            }
#pragma unroll
            for (int mt = 0; mt < 4; mt++)
#pragma unroll
                for (int nt = 0; nt < 4; nt++) {
                    int p = nt >> 1, q = nt & 1;
                    mma16816(acc[mt][nt], a[mt], b[p][q], b[p][q + 2]);
                }
        }
        st = (st + 1 >= 3) ? 0 : st + 1;
    }

#pragma unroll
    for (int mt = 0; mt < 4; mt++) {
#pragma unroll
        for (int nt = 0; nt < 4; nt++) {
            int m0 = bm * 128 + wm * 64 + mt * 16 + (lane >> 2);
            int n0 = bn * 128 + wn * 32 + nt * 8 + 2 * (lane & 3);
            float c0 = acc[mt][nt][0], c1 = acc[mt][nt][1];
            float c2 = acc[mt][nt][2], c3 = acc[mt][nt][3];
            if (EPI == 0) {
                int part = n0 >> 10;
                __half* dh = (part == 0) ? g_Qh : (part == 1) ? g_Kh : g_Vh;
                float scl = (part == 0) ? 0.125f : 1.0f;
                int head = (n0 & 1023) >> 6, d = n0 & 63;
#pragma unroll
                for (int rr = 0; rr < 2; rr++) {
                    int m = m0 + rr * 8;
                    int bi = m >> 11, s = m & (SEQ - 1);
                    float v0 = (rr ? c2 : c0) * scl, v1 = (rr ? c3 : c1) * scl;
                    __half h0 = __float2half_rn(v0);
                    __half h1 = __float2half_rn(v1);
                    size_t idx = (((size_t)(bi*NH + head))*SEQ + s)*HD + d;
                    *(uint32_t*)&dh[idx] = pkh2(h0, h1);
                    if (part == 0) {
                        __half l0 = __float2half_rn(v0 - __half2float(h0));
                        __half l1 = __float2half_rn(v1 - __half2float(h1));
                        *(uint32_t*)&g_Ql[idx] = pkh2(l0, l1);
                    }
                }
            } else {
                float2 bv = *(const float2*)&bias[n0];
                *(float2*)&Cout[(size_t)m0 * DIM + n0]       = make_float2(c0 + bv.x, c1 + bv.y);
                *(float2*)&Cout[(size_t)(m0 + 8) * DIM + n0] = make_float2(c2 + bv.x, c3 + bv.y);
            }
        }
    }
}

// ---------------------------------------------------------------------------
// HMMA fp16 flash attention, split-2 kept on the softmax path:
// S = (Qh+Ql).Kh (2 passes), O += (Ph+Pl).Vh (2 passes).
// CTA = 64 queries x one (b,h), 4 warps, 2-stage cp.async KV, 32KB smem.
// qi remapped longest-first. allowed(q,k) = (k <= q) || (k < 256).
// Output O written fp16 hi-only, row-major [b*SEQ+row][DIM] for proj GEMM.
// ---------------------------------------------------------------------------
__global__ __launch_bounds__(128) void attn_mma()
{
    __shared__ __align__(16) __half sQh[64*64];       // 8192 B
    __shared__ __align__(16) __half sQl[64*64];       // 8192 B
    __shared__ __align__(16) __half sKh[2][32*64];    // 8192 B
    __shared__ __align__(16) __half sVh[2][32*64];    // 8192 B => 32 KB

    const int qi  = (SEQ/64 - 1) - blockIdx.x;        // longest first
    const int bh  = blockIdx.y;
    const int b   = bh >> 4, h = bh & 15;
    const int tid = threadIdx.x, w = tid >> 5, lane = tid & 31;
    const int qbase = qi * 64;

    const size_t base = (size_t)bh * SEQ * HD;
    const uint32_t qh0 = smem_u32(sQh), ql0 = smem_u32(sQl);
    const uint32_t kh0 = smem_u32(sKh), vh0 = smem_u32(sVh);
    const uint32_t KVST = 32 * 128;                   // 4096 B per stage

    for (int i = tid; i < 512; i += 128) {
        int r = i >> 3, seg = i & 7;
        int pseg = seg ^ (r & 7);
        const char* gq = (const char*)(g_Qh + base + (size_t)(qbase + r) * HD);
        const char* gl = (const char*)(g_Ql + base + (size_t)(qbase + r) * HD);
        cp16(qh0 + (uint32_t)(r * 128 + pseg * 16), gq + seg * 16);
        cp16(ql0 + (uint32_t)(r * 128 + pseg * 16), gl + seg * 16);
    }
    CP_COMMIT();

#define LOADKV(ch, st)                                                              \
    {                                                                               \
        int kb = (ch) * 32;                                                         \
        _Pragma("unroll")                                                           \
        for (int i = tid; i < 256; i += 128) {                                      \
            int r = i >> 3, seg = i & 7;                                            \
            int pseg = seg ^ (r & 7);                                               \
            size_t gidx = base + (size_t)(kb + r) * HD;                             \
            uint32_t so = (uint32_t)((st) * KVST + r * 128 + pseg * 16);            \
            cp16(kh0 + so, (const char*)(g_Kh + gidx) + seg * 16);                  \
            cp16(vh0 + so, (const char*)(g_Vh + gidx) + seg * 16);                  \
        }                                                                           \
    }

    const int nch = (qi < 4) ? 8 : 2 * (qi + 1);
    LOADKV(0, 0); CP_COMMIT();

    float o[8][4];
#pragma unroll
    for (int i = 0; i < 8; i++)
#pragma unroll
        for (int j = 0; j < 4; j++) o[i][j] = 0.f;
    float mi[2] = {-1e30f, -1e30f}, li[2] = {0.f, 0.f};

    const int lrow  = lane & 15;
    const int lhalf = lane >> 4;

    for (int ch = 0; ch < nch; ch++) {
        CP_WAIT(0);
        __syncthreads();
        if (ch + 1 < nch) { LOADKV(ch + 1, (ch + 1) & 1); }
        CP_COMMIT();

        const int kbase = ch * 32;
        const uint32_t kvoff = (uint32_t)((ch & 1) * KVST);

        // ---- S = (Qh+Ql) Kh^T : 2 passes ----
        float s[4][4];
#pragma unroll
        for (int nt = 0; nt < 4; nt++)
#pragma unroll
            for (int j = 0; j < 4; j++) s[nt][j] = 0.f;

#pragma unroll
        for (int kg = 0; kg < 4; kg++) {
            int lseg = kg * 2 + lhalf;
            uint32_t aH[4], aL[4], bH[2][4];
            {
                int row = w*16 + lrow;
                uint32_t ao = (uint32_t)(row * 128 + (lseg ^ (row & 7)) * 16);
                ldsm4(aH, qh0 + ao);
                ldsm4(aL, ql0 + ao);
            }
#pragma unroll
            for (int p = 0; p < 2; p++) {
                int row = p*16 + lrow;
                ldsm4(bH[p], kh0 + kvoff + (uint32_t)(row * 128 + (lseg ^ (row & 7)) * 16));
            }
#pragma unroll
            for (int nt = 0; nt < 4; nt++) {
                int p = nt >> 1, q = nt & 1;
                mma16816(s[nt], aH, bH[p][q], bH[p][q+2]);
                mma16816(s[nt], aL, bH[p][q], bH[p][q+2]);
            }
        }

        if (kbase >= PREFIX && kbase + 31 > qbase) {
            int q0 = qbase + w*16 + (lane >> 2);
#pragma unroll
            for (int nt = 0; nt < 4; nt++) {
                int k0 = kbase + nt*8 + 2*(lane & 3);
                if (k0     > q0)     s[nt][0] = -1e30f;
                if (k0 + 1 > q0)     s[nt][1] = -1e30f;
                if (k0     > q0 + 8) s[nt][2] = -1e30f;
                if (k0 + 1 > q0 + 8) s[nt][3] = -1e30f;
            }
        }

#pragma unroll
        for (int rr = 0; rr < 2; rr++) {
            float mx = -1e30f;
#pragma unroll
            for (int nt = 0; nt < 4; nt++)
                mx = fmaxf(mx, fmaxf(s[nt][2*rr], s[nt][2*rr+1]));
            mx = fmaxf(mx, __shfl_xor_sync(0xffffffffu, mx, 1));
            mx = fmaxf(mx, __shfl_xor_sync(0xffffffffu, mx, 2));
            float mnew  = fmaxf(mi[rr], mx);
            float alpha = __expf(mi[rr] - mnew);
            float rs = 0.f;
#pragma unroll
            for (int nt = 0; nt < 4; nt++) {
                float p0 = __expf(s[nt][2*rr]   - mnew);
                float p1 = __expf(s[nt][2*rr+1] - mnew);
                s[nt][2*rr] = p0; s[nt][2*rr+1] = p1;
                rs += p0 + p1;
            }
            rs += __shfl_xor_sync(0xffffffffu, rs, 1);
            rs += __shfl_xor_sync(0xffffffffu, rs, 2);
            li[rr] = li[rr] * alpha + rs;
            mi[rr] = mnew;
#pragma unroll
            for (int dn = 0; dn < 8; dn++) {
                o[dn][2*rr] *= alpha; o[dn][2*rr+1] *= alpha;
            }
        }

        // ---- O += (Ph+Pl) Vh : 2 passes ----
#pragma unroll
        for (int kt = 0; kt < 2; kt++) {
            uint32_t pH[4], pL[4];
#pragma unroll
            for (int half = 0; half < 2; half++) {
                float* sv = s[2*kt + half];
                __half h0 = __float2half_rn(sv[0]);
                __half h1 = __float2half_rn(sv[1]);
                __half h2 = __float2half_rn(sv[2]);
                __half h3 = __float2half_rn(sv[3]);
                __half l0 = __float2half_rn(sv[0] - __half2float(h0));
                __half l1 = __float2half_rn(sv[1] - __half2float(h1));
                __half l2 = __float2half_rn(sv[2] - __half2float(h2));
                __half l3 = __float2half_rn(sv[3] - __half2float(h3));
                pH[half*2+0] = pkh2(h0, h1); pH[half*2+1] = pkh2(h2, h3);
                pL[half*2+0] = pkh2(l0, l1); pL[half*2+1] = pkh2(l2, l3);
            }
#pragma unroll
            for (int p4 = 0; p4 < 4; p4++) {
                int row = kt*16 + lrow;
                int lseg = p4*2 + lhalf;
                uint32_t vo = kvoff + (uint32_t)(row * 128 + (lseg ^ (row & 7)) * 16);
                uint32_t vH[4];
                ldsm4t(vH, vh0 + vo);
                mma16816(o[2*p4],   pH, vH[0], vH[1]);
                mma16816(o[2*p4],   pL, vH[0], vH[1]);
                mma16816(o[2*p4+1], pH, vH[2], vH[3]);
                mma16816(o[2*p4+1], pL, vH[2], vH[3]);
            }
        }
    }

    // ---- epilogue: normalize, write O fp16 hi-only [b*SEQ+row][DIM] ----
#pragma unroll
    for (int dn = 0; dn < 8; dn++) {
        int d0 = dn*8 + 2*(lane & 3);
#pragma unroll
        for (int rr = 0; rr < 2; rr++) {
            int row = qbase + w*16 + (lane >> 2) + rr*8;
            float inv = 1.0f / li[rr];
            __half h0 = __float2half_rn(o[dn][2*rr]   * inv);
            __half h1 = __float2half_rn(o[dn][2*rr+1] * inv);
            size_t off = (size_t)(b*SEQ + row) * DIM + (h*HD + d0);
            *(uint32_t*)&g_o16[off] = pkh2(h0, h1);
        }
    }
}

// ---------------------------------------------------------------------------
extern "C" void kernel_launch(void* const* d_in, const int* in_sizes, int n_in,
                              void* d_out, int out_size)
{
    const float* x      = (const float*)d_in[0];
    const float* qkv_w  = (const float*)d_in[1];
    const float* proj_w = (const float*)d_in[2];
    const float* proj_b = (const float*)d_in[3];
    float*       out    = (float*)d_out;

    void *px16, *pw16, *po16, *ppw16;
    cudaGetSymbolAddress(&px16,  g_x16);
    cudaGetSymbolAddress(&pw16,  g_w16);
    cudaGetSymbolAddress(&po16,  g_o16);
    cudaGetSymbolAddress(&ppw16, g_pw16);

    cvt16_kernel<<<(MROWS*DIM/4 + 255)/256, 256>>>(x,      (__half*)px16,  MROWS*DIM/4);
    cvt16_kernel<<<(3*DIM*DIM/4 + 255)/256, 256>>>(qkv_w,  (__half*)pw16,  3*DIM*DIM/4);
    cvt16_kernel<<<(DIM*DIM/4   + 255)/256, 256>>>(proj_w, (__half*)ppw16, DIM*DIM/4);

    // 1) QKV projection (plain fp16 HMMA): M=4096, N=3072, K=1024
    mma_gemm<0><<<dim3(3*DIM/128, MROWS/128), 256>>>(
        (const __half*)px16, (const __half*)pw16, nullptr, nullptr);

    // 2) flash attention (fp16, split-2 softmax path)
    attn_mma<<<dim3(SEQ/64, BS*NH), 128>>>();

    // 3) proj GEMM + bias: M=4096, N=1024, K=1024
    mma_gemm<1><<<dim3(DIM/128, MROWS/128), 256>>>(
        (const __half*)po16, (const __half*)ppw16, proj_b, out);
}

// round 14
// speedup vs baseline: 2.6528x; 1.2518x over previous
#include <cuda_runtime.h>
#include <cuda_fp16.h>
#include <cstdint>

#define BS   2
#define SEQ  2048
#define DIM  1024
#define NH   16
#define HD   64
#define PREFIX 256
#define MROWS (BS*SEQ)
#define KT   DIM              // plain fp16 GEMM K

// ------------------------- device scratch (no allocs) -----------------------
__device__ __half g_Qh[BS*NH*SEQ*HD];
__device__ __half g_Kh[BS*NH*SEQ*HD];
__device__ __half g_Vh[BS*NH*SEQ*HD];
__device__ __half g_x16 [MROWS*DIM];     // x fp16        (4096 x 1024)
__device__ __half g_w16 [3*DIM*DIM];     // qkv_w fp16    (3072 x 1024)
__device__ __half g_o16 [MROWS*DIM];     // attn out fp16 (4096 x 1024)
__device__ __half g_pw16[DIM*DIM];       // proj_w fp16   (1024 x 1024)

// ------------------------- portable PTX helpers (sm_80+) --------------------
__device__ __forceinline__ uint32_t smem_u32(const void* p) {
    uint32_t a;
    asm("{ .reg .u64 t; cvta.to.shared.u64 t, %1; cvt.u32.u64 %0, t; }" : "=r"(a) : "l"(p));
    return a;
}
__device__ __forceinline__ void cp16(uint32_t saddr, const void* g) {
    asm volatile("cp.async.cg.shared.global [%0], [%1], 16;" :: "r"(saddr), "l"(g));
}
#define CP_COMMIT()  asm volatile("cp.async.commit_group;" ::: "memory")
#define CP_WAIT(n)   asm volatile("cp.async.wait_group %0;" :: "n"(n) : "memory")

__device__ __forceinline__ void ldsm4(uint32_t* r, uint32_t addr) {
    asm volatile("ldmatrix.sync.aligned.m8n8.x4.shared.b16 {%0,%1,%2,%3}, [%4];"
                 : "=r"(r[0]), "=r"(r[1]), "=r"(r[2]), "=r"(r[3]) : "r"(addr));
}
__device__ __forceinline__ void ldsm4t(uint32_t* r, uint32_t addr) {
    asm volatile("ldmatrix.sync.aligned.m8n8.x4.trans.shared.b16 {%0,%1,%2,%3}, [%4];"
                 : "=r"(r[0]), "=r"(r[1]), "=r"(r[2]), "=r"(r[3]) : "r"(addr));
}
__device__ __forceinline__ void mma16816(float* c, const uint32_t* a, uint32_t b0, uint32_t b1) {
    asm volatile("mma.sync.aligned.m16n8k16.row.col.f32.f16.f16.f32 "
                 "{%0,%1,%2,%3}, {%4,%5,%6,%7}, {%8,%9}, {%0,%1,%2,%3};"
                 : "+f"(c[0]), "+f"(c[1]), "+f"(c[2]), "+f"(c[3])
                 : "r"(a[0]), "r"(a[1]), "r"(a[2]), "r"(a[3]), "r"(b0), "r"(b1));
}
__device__ __forceinline__ uint32_t pkh2(__half a, __half b) {
    __half2 t; t.x = a; t.y = b;
    return *(uint32_t*)&t;
}

// ---------------------------------------------------------------------------
// fp32 -> fp16 conversion (round to nearest)
// ---------------------------------------------------------------------------
__global__ __launch_bounds__(256) void cvt16_kernel(const float* __restrict__ src,
                                                    __half* __restrict__ dst,
                                                    int n4)
{
    int i = blockIdx.x * blockDim.x + threadIdx.x;
    if (i >= n4) return;
    float4 v = ((const float4*)src)[i];
    __half t[4];
    t[0] = __float2half_rn(v.x); t[1] = __float2half_rn(v.y);
    t[2] = __float2half_rn(v.z); t[3] = __float2half_rn(v.w);
    *(uint2*)(dst + (size_t)i * 4) = *(const uint2*)t;
}

// ---------------------------------------------------------------------------
// HMMA fp16 GEMM: CTA 128x128, 8 warps (2x4), warp tile 64x32. K=1024, 32
// chunks. 3-stage cp.async, 64B rows + XOR swizzle, 48KB static smem.
// EPI 0: scatter Q(x0.125)/K/V fp16.  EPI 1: out = C + bias (fp32).
// ---------------------------------------------------------------------------
template<int EPI>
__global__ __launch_bounds__(256, 2) void mma_gemm(const __half* __restrict__ A2,
                                                   const __half* __restrict__ B2,
                                                   const float* __restrict__ bias,
                                                   float* __restrict__ Cout)
{
    __shared__ __align__(16) __half sA[3][128*32];   // 8192 B / stage
    __shared__ __align__(16) __half sB[3][128*32];

    const int tid  = threadIdx.x;
    const int wid  = tid >> 5, lane = tid & 31;
    const int wm   = wid & 1,  wn   = wid >> 1;      // 2x4 warp grid
    const int bn   = blockIdx.x, bm = blockIdx.y;
    const int NCH  = KT / 32;                        // 32 chunks
    const uint32_t STB = 128 * 64;                   // stage bytes = 8192

    const char* Ab = (const char*)(A2 + (size_t)bm * 128 * KT);
    const char* Bb = (const char*)(B2 + (size_t)bn * 128 * KT);

    const uint32_t sA0 = smem_u32(&sA[0][0]);
    const uint32_t sB0 = smem_u32(&sB[0][0]);

    float acc[4][4][4];
#pragma unroll
    for (int i = 0; i < 4; i++)
#pragma unroll
        for (int j = 0; j < 4; j++)
#pragma unroll
            for (int k = 0; k < 4; k++) acc[i][j][k] = 0.f;

#define LOAD_TILE(c, st)                                                           \
    {                                                                              \
        int koff = (c) * 64;                                                       \
        _Pragma("unroll")                                                          \
        for (int i = 0; i < 2; i++) {                                              \
            int idx = tid + i * 256;                                               \
            int row = idx >> 2, seg = idx & 3;                                     \
            int pseg = seg ^ ((row >> 1) & 3);                                     \
            uint32_t so = (uint32_t)((st) * STB + row * 64 + pseg * 16);           \
            cp16(sA0 + so, Ab + (size_t)row * (KT*2) + koff + seg * 16);           \
            cp16(sB0 + so, Bb + (size_t)row * (KT*2) + koff + seg * 16);           \
        }                                                                          \
    }

    LOAD_TILE(0, 0); CP_COMMIT();
    LOAD_TILE(1, 1); CP_COMMIT();

    const int lrow = lane & 15;
    const int lhalf = lane >> 4;                     // 0/1 -> +16B column

    int st = 0;
    for (int c = 0; c < NCH; c++) {
        CP_WAIT(1);
        __syncthreads();

        if (c + 2 < NCH) {
            int st2 = (st + 2 >= 3) ? st - 1 : st + 2;
            LOAD_TILE(c + 2, st2);
        }
        CP_COMMIT();

        uint32_t abase = sA0 + st * STB;
        uint32_t bbase = sB0 + st * STB;
#pragma unroll
        for (int kg = 0; kg < 2; kg++) {
            uint32_t a[4][4], b[2][4];
            int lseg = kg * 2 + lhalf;
#pragma unroll
            for (int mt = 0; mt < 4; mt++) {
                int row = wm*64 + mt*16 + lrow;
                ldsm4(a[mt], abase + (uint32_t)(row * 64 + (lseg ^ ((row >> 1) & 3)) * 16));
            }
#pragma unroll
            for (int p = 0; p < 2; p++) {
                int row = wn*32 + p*16 + lrow;
                ldsm4(b[p], bbase + (uint32_t)(row * 64 + (lseg ^ ((row >> 1) & 3)) * 16));
            }
#pragma unroll
            for (int mt = 0; mt < 4; mt++)
#pragma unroll
                for (int nt = 0; nt < 4; nt++) {
                    int p = nt >> 1, q = nt & 1;
                    mma16816(acc[mt][nt], a[mt], b[p][q], b[p][q + 2]);
                }
        }
        st = (st + 1 >= 3) ? 0 : st + 1;
    }

#pragma unroll
    for (int mt = 0; mt < 4; mt++) {
#pragma unroll
        for (int nt = 0; nt < 4; nt++) {
            int m0 = bm * 128 + wm * 64 + mt * 16 + (lane >> 2);
            int n0 = bn * 128 + wn * 32 + nt * 8 + 2 * (lane & 3);
            float c0 = acc[mt][nt][0], c1 = acc[mt][nt][1];
            float c2 = acc[mt][nt][2], c3 = acc[mt][nt][3];
            if (EPI == 0) {
                int part = n0 >> 10;
                __half* dh = (part == 0) ? g_Qh : (part == 1) ? g_Kh : g_Vh;
                float scl = (part == 0) ? 0.125f : 1.0f;
                int head = (n0 & 1023) >> 6, d = n0 & 63;
#pragma unroll
                for (int rr = 0; rr < 2; rr++) {
                    int m = m0 + rr * 8;
                    int bi = m >> 11, s = m & (SEQ - 1);
                    float v0 = (rr ? c2 : c0) * scl, v1 = (rr ? c3 : c1) * scl;
                    size_t idx = (((size_t)(bi*NH + head))*SEQ + s)*HD + d;
                    *(uint32_t*)&dh[idx] = pkh2(__float2half_rn(v0), __float2half_rn(v1));
                }
            } else {
                float2 bv = *(const float2*)&bias[n0];
                *(float2*)&Cout[(size_t)m0 * DIM + n0]       = make_float2(c0 + bv.x, c1 + bv.y);
                *(float2*)&Cout[(size_t)(m0 + 8) * DIM + n0] = make_float2(c2 + bv.x, c3 + bv.y);
            }
        }
    }
}

// ---------------------------------------------------------------------------
// HMMA fp16 flash attention (single-pass fp16: S = Qh.Kh, O += Ph.Vh).
// CTA = 64 queries x one (b,h), 4 warps, 2-stage cp.async KV, 24KB smem.
// qi remapped longest-first. allowed(q,k) = (k <= q) || (k < 256).
// Q pre-scaled by 1/8. O written fp16, row-major [b*SEQ+row][DIM].
// ---------------------------------------------------------------------------
__global__ __launch_bounds__(128) void attn_mma()
{
    __shared__ __align__(16) __half sQh[64*64];       // 8192 B
    __shared__ __align__(16) __half sKh[2][32*64];    // 8192 B
    __shared__ __align__(16) __half sVh[2][32*64];    // 8192 B => 24 KB

    const int qi  = (SEQ/64 - 1) - blockIdx.x;        // longest first
    const int bh  = blockIdx.y;
    const int b   = bh >> 4, h = bh & 15;
    const int tid = threadIdx.x, w = tid >> 5, lane = tid & 31;
    const int qbase = qi * 64;

    const size_t base = (size_t)bh * SEQ * HD;
    const uint32_t qh0 = smem_u32(sQh);
    const uint32_t kh0 = smem_u32(sKh), vh0 = smem_u32(sVh);
    const uint32_t KVST = 32 * 128;                   // 4096 B per stage

    for (int i = tid; i < 512; i += 128) {
        int r = i >> 3, seg = i & 7;
        int pseg = seg ^ (r & 7);
        const char* gq = (const char*)(g_Qh + base + (size_t)(qbase + r) * HD);
        cp16(qh0 + (uint32_t)(r * 128 + pseg * 16), gq + seg * 16);
    }
    CP_COMMIT();

#define LOADKV(ch, st)                                                              \
    {                                                                               \
        int kb = (ch) * 32;                                                         \
        _Pragma("unroll")                                                           \
        for (int i = tid; i < 256; i += 128) {                                      \
            int r = i >> 3, seg = i & 7;                                            \
            int pseg = seg ^ (r & 7);                                               \
            size_t gidx = base + (size_t)(kb + r) * HD;                             \
            uint32_t so = (uint32_t)((st) * KVST + r * 128 + pseg * 16);            \
            cp16(kh0 + so, (const char*)(g_Kh + gidx) + seg * 16);                  \
            cp16(vh0 + so, (const char*)(g_Vh + gidx) + seg * 16);                  \
        }                                                                           \
    }

    const int nch = (qi < 4) ? 8 : 2 * (qi + 1);
    LOADKV(0, 0); CP_COMMIT();

    float o[8][4];
#pragma unroll
    for (int i = 0; i < 8; i++)
#pragma unroll
        for (int j = 0; j < 4; j++) o[i][j] = 0.f;
    float mi[2] = {-1e30f, -1e30f}, li[2] = {0.f, 0.f};

    const int lrow  = lane & 15;
    const int lhalf = lane >> 4;

    for (int ch = 0; ch < nch; ch++) {
        CP_WAIT(0);
        __syncthreads();
        if (ch + 1 < nch) { LOADKV(ch + 1, (ch + 1) & 1); }
        CP_COMMIT();

        const int kbase = ch * 32;
        const uint32_t kvoff = (uint32_t)((ch & 1) * KVST);

        // ---- S = Qh Kh^T ----
        float s[4][4];
#pragma unroll
        for (int nt = 0; nt < 4; nt++)
#pragma unroll
            for (int j = 0; j < 4; j++) s[nt][j] = 0.f;

#pragma unroll
        for (int kg = 0; kg < 4; kg++) {
            int lseg = kg * 2 + lhalf;
            uint32_t aH[4], bH[2][4];
            {
                int row = w*16 + lrow;
                ldsm4(aH, qh0 + (uint32_t)(row * 128 + (lseg ^ (row & 7)) * 16));
            }
#pragma unroll
            for (int p = 0; p < 2; p++) {
                int row = p*16 + lrow;
                ldsm4(bH[p], kh0 + kvoff + (uint32_t)(row * 128 + (lseg ^ (row & 7)) * 16));
            }
#pragma unroll
            for (int nt = 0; nt < 4; nt++) {
                int p = nt >> 1, q = nt & 1;
                mma16816(s[nt], aH, bH[p][q], bH[p][q+2]);
            }
        }

        if (kbase >= PREFIX && kbase + 31 > qbase) {
            int q0 = qbase + w*16 + (lane >> 2);
#pragma unroll
            for (int nt = 0; nt < 4; nt++) {
                int k0 = kbase + nt*8 + 2*(lane & 3);
                if (k0     > q0)     s[nt][0] = -1e30f;
                if (k0 + 1 > q0)     s[nt][1] = -1e30f;
                if (k0     > q0 + 8) s[nt][2] = -1e30f;
                if (k0 + 1 > q0 + 8) s[nt][3] = -1e30f;
            }
        }

        // ---- online softmax (rows r and r+8), quad shfl reductions ----
#pragma unroll
        for (int rr = 0; rr < 2; rr++) {
            float mx = -1e30f;
#pragma unroll
            for (int nt = 0; nt < 4; nt++)
                mx = fmaxf(mx, fmaxf(s[nt][2*rr], s[nt][2*rr+1]));
            mx = fmaxf(mx, __shfl_xor_sync(0xffffffffu, mx, 1));
            mx = fmaxf(mx, __shfl_xor_sync(0xffffffffu, mx, 2));
            float mnew  = fmaxf(mi[rr], mx);
            float alpha = __expf(mi[rr] - mnew);
            float rs = 0.f;
#pragma unroll
            for (int nt = 0; nt < 4; nt++) {
                float p0 = __expf(s[nt][2*rr]   - mnew);
                float p1 = __expf(s[nt][2*rr+1] - mnew);
                s[nt][2*rr] = p0; s[nt][2*rr+1] = p1;
                rs += p0 + p1;
            }
            rs += __shfl_xor_sync(0xffffffffu, rs, 1);
            rs += __shfl_xor_sync(0xffffffffu, rs, 2);
            li[rr] = li[rr] * alpha + rs;
            mi[rr] = mnew;
#pragma unroll
            for (int dn = 0; dn < 8; dn++) {
                o[dn][2*rr] *= alpha; o[dn][2*rr+1] *= alpha;
            }
        }

        // ---- O += Ph Vh ----
#pragma unroll
        for (int kt = 0; kt < 2; kt++) {
            uint32_t pH[4];
#pragma unroll
            for (int half = 0; half < 2; half++) {
                float* sv = s[2*kt + half];
                pH[half*2+0] = pkh2(__float2half_rn(sv[0]), __float2half_rn(sv[1]));
                pH[half*2+1] = pkh2(__float2half_rn(sv[2]), __float2half_rn(sv[3]));
            }
#pragma unroll
            for (int p4 = 0; p4 < 4; p4++) {
                int row = kt*16 + lrow;
                int lseg = p4*2 + lhalf;
                uint32_t vo = kvoff + (uint32_t)(row * 128 + (lseg ^ (row & 7)) * 16);
                uint32_t vH[4];
                ldsm4t(vH, vh0 + vo);
                mma16816(o[2*p4],   pH, vH[0], vH[1]);
                mma16816(o[2*p4+1], pH, vH[2], vH[3]);
            }
        }
    }

    // ---- epilogue: normalize, write O fp16 [b*SEQ+row][DIM] ----
#pragma unroll
    for (int dn = 0; dn < 8; dn++) {
        int d0 = dn*8 + 2*(lane & 3);
#pragma unroll
        for (int rr = 0; rr < 2; rr++) {
            int row = qbase + w*16 + (lane >> 2) + rr*8;
            float inv = 1.0f / li[rr];
            __half h0 = __float2half_rn(o[dn][2*rr]   * inv);
            __half h1 = __float2half_rn(o[dn][2*rr+1] * inv);
            size_t off = (size_t)(b*SEQ + row) * DIM + (h*HD + d0);
            *(uint32_t*)&g_o16[off] = pkh2(h0, h1);
        }
    }
}

// ---------------------------------------------------------------------------
extern "C" void kernel_launch(void* const* d_in, const int* in_sizes, int n_in,
                              void* d_out, int out_size)
{
    const float* x      = (const float*)d_in[0];
    const float* qkv_w  = (const float*)d_in[1];
    const float* proj_w = (const float*)d_in[2];
    const float* proj_b = (const float*)d_in[3];
    float*       out    = (float*)d_out;

    void *px16, *pw16, *po16, *ppw16;
    cudaGetSymbolAddress(&px16,  g_x16);
    cudaGetSymbolAddress(&pw16,  g_w16);
    cudaGetSymbolAddress(&po16,  g_o16);
    cudaGetSymbolAddress(&ppw16, g_pw16);

    cvt16_kernel<<<(MROWS*DIM/4 + 255)/256, 256>>>(x,      (__half*)px16,  MROWS*DIM/4);
    cvt16_kernel<<<(3*DIM*DIM/4 + 255)/256, 256>>>(qkv_w,  (__half*)pw16,  3*DIM*DIM/4);
    cvt16_kernel<<<(DIM*DIM/4   + 255)/256, 256>>>(proj_w, (__half*)ppw16, DIM*DIM/4);

    // 1) QKV projection (fp16 HMMA): M=4096, N=3072, K=1024
    mma_gemm<0><<<dim3(3*DIM/128, MROWS/128), 256>>>(
        (const __half*)px16, (const __half*)pw16, nullptr, nullptr);

    // 2) flash attention (fp16 single-pass)
    attn_mma<<<dim3(SEQ/64, BS*NH), 128>>>();

    // 3) proj GEMM + bias: M=4096, N=1024, K=1024
    mma_gemm<1><<<dim3(DIM/128, MROWS/128), 256>>>(
        (const __half*)po16, (const __half*)ppw16, proj_b, out);
}

// round 15
// speedup vs baseline: 2.7083x; 1.0209x over previous
#include <cuda_runtime.h>
#include <cuda_fp16.h>
#include <cstdint>

#define BS   2
#define SEQ  2048
#define DIM  1024
#define NH   16
#define HD   64
#define PREFIX 256
#define MROWS (BS*SEQ)
#define KT   DIM              // plain fp16 GEMM K

// ------------------------- device scratch (no allocs) -----------------------
__device__ __half g_Qh[BS*NH*SEQ*HD];
__device__ __half g_Kh[BS*NH*SEQ*HD];
__device__ __half g_Vh[BS*NH*SEQ*HD];
__device__ __half g_x16 [MROWS*DIM];     // x fp16        (4096 x 1024)
__device__ __half g_w16 [3*DIM*DIM];     // qkv_w fp16    (3072 x 1024)
__device__ __half g_o16 [MROWS*DIM];     // attn out fp16 (4096 x 1024)
__device__ __half g_pw16[DIM*DIM];       // proj_w fp16   (1024 x 1024)

// ------------------------- portable PTX helpers (sm_80+) --------------------
__device__ __forceinline__ uint32_t smem_u32(const void* p) {
    uint32_t a;
    asm("{ .reg .u64 t; cvta.to.shared.u64 t, %1; cvt.u32.u64 %0, t; }" : "=r"(a) : "l"(p));
    return a;
}
__device__ __forceinline__ void cp16(uint32_t saddr, const void* g) {
    asm volatile("cp.async.cg.shared.global [%0], [%1], 16;" :: "r"(saddr), "l"(g));
}
#define CP_COMMIT()  asm volatile("cp.async.commit_group;" ::: "memory")
#define CP_WAIT(n)   asm volatile("cp.async.wait_group %0;" :: "n"(n) : "memory")

__device__ __forceinline__ void ldsm4(uint32_t* r, uint32_t addr) {
    asm volatile("ldmatrix.sync.aligned.m8n8.x4.shared.b16 {%0,%1,%2,%3}, [%4];"
                 : "=r"(r[0]), "=r"(r[1]), "=r"(r[2]), "=r"(r[3]) : "r"(addr));
}
__device__ __forceinline__ void ldsm4t(uint32_t* r, uint32_t addr) {
    asm volatile("ldmatrix.sync.aligned.m8n8.x4.trans.shared.b16 {%0,%1,%2,%3}, [%4];"
                 : "=r"(r[0]), "=r"(r[1]), "=r"(r[2]), "=r"(r[3]) : "r"(addr));
}
__device__ __forceinline__ void mma16816(float* c, const uint32_t* a, uint32_t b0, uint32_t b1) {
    asm volatile("mma.sync.aligned.m16n8k16.row.col.f32.f16.f16.f32 "
                 "{%0,%1,%2,%3}, {%4,%5,%6,%7}, {%8,%9}, {%0,%1,%2,%3};"
                 : "+f"(c[0]), "+f"(c[1]), "+f"(c[2]), "+f"(c[3])
                 : "r"(a[0]), "r"(a[1]), "r"(a[2]), "r"(a[3]), "r"(b0), "r"(b1));
}
__device__ __forceinline__ uint32_t pkh2(__half a, __half b) {
    __half2 t; t.x = a; t.y = b;
    return *(uint32_t*)&t;
}

// ---------------------------------------------------------------------------
// merged fp32 -> fp16 conversion for x, qkv_w, proj_w in ONE launch.
// index space (float4 units): [0, N1) -> x, [N1, N1+N2) -> qkv_w, rest proj_w
// ---------------------------------------------------------------------------
#define CVT_N1 (MROWS*DIM/4)
#define CVT_N2 (3*DIM*DIM/4)
#define CVT_N3 (DIM*DIM/4)
__global__ __launch_bounds__(256) void cvt_all_kernel(const float* __restrict__ x,
                                                      const float* __restrict__ w,
                                                      const float* __restrict__ pw)
{
    int i = blockIdx.x * blockDim.x + threadIdx.x;
    const float* src;
    __half* dst;
    int j;
    if (i < CVT_N1)                    { src = x;  dst = g_x16;  j = i; }
    else if (i < CVT_N1 + CVT_N2)      { src = w;  dst = g_w16;  j = i - CVT_N1; }
    else if (i < CVT_N1+CVT_N2+CVT_N3) { src = pw; dst = g_pw16; j = i - CVT_N1 - CVT_N2; }
    else return;
    float4 v = ((const float4*)src)[j];
    __half t[4];
    t[0] = __float2half_rn(v.x); t[1] = __float2half_rn(v.y);
    t[2] = __float2half_rn(v.z); t[3] = __float2half_rn(v.w);
    *(uint2*)(dst + (size_t)j * 4) = *(const uint2*)t;
}

// ---------------------------------------------------------------------------
// HMMA fp16 GEMM (UNCHANGED from round 14 — at mma.sync ceiling).
// CTA 128x128, 8 warps (2x4), warp tile 64x32. K=1024, 32 chunks.
// 3-stage cp.async, 64B rows + XOR swizzle, 48KB static smem.
// EPI 0: scatter Q(x0.125)/K/V fp16.  EPI 1: out = C + bias (fp32).
// ---------------------------------------------------------------------------
template<int EPI>
__global__ __launch_bounds__(256, 2) void mma_gemm(const __half* __restrict__ A2,
                                                   const __half* __restrict__ B2,
                                                   const float* __restrict__ bias,
                                                   float* __restrict__ Cout)
{
    __shared__ __align__(16) __half sA[3][128*32];   // 8192 B / stage
    __shared__ __align__(16) __half sB[3][128*32];

    const int tid  = threadIdx.x;
    const int wid  = tid >> 5, lane = tid & 31;
    const int wm   = wid & 1,  wn   = wid >> 1;      // 2x4 warp grid
    const int bn   = blockIdx.x, bm = blockIdx.y;
    const int NCH  = KT / 32;                        // 32 chunks
    const uint32_t STB = 128 * 64;                   // stage bytes = 8192

    const char* Ab = (const char*)(A2 + (size_t)bm * 128 * KT);
    const char* Bb = (const char*)(B2 + (size_t)bn * 128 * KT);

    const uint32_t sA0 = smem_u32(&sA[0][0]);
    const uint32_t sB0 = smem_u32(&sB[0][0]);

    float acc[4][4][4];
#pragma unroll
    for (int i = 0; i < 4; i++)
#pragma unroll
        for (int j = 0; j < 4; j++)
#pragma unroll
            for (int k = 0; k < 4; k++) acc[i][j][k] = 0.f;

#define LOAD_TILE(c, st)                                                           \
    {                                                                              \
        int koff = (c) * 64;                                                       \
        _Pragma("unroll")                                                          \
        for (int i = 0; i < 2; i++) {                                              \
            int idx = tid + i * 256;                                               \
            int row = idx >> 2, seg = idx & 3;                                     \
            int pseg = seg ^ ((row >> 1) & 3);                                     \
            uint32_t so = (uint32_t)((st) * STB + row * 64 + pseg * 16);           \
            cp16(sA0 + so, Ab + (size_t)row * (KT*2) + koff + seg * 16);           \
            cp16(sB0 + so, Bb + (size_t)row * (KT*2) + koff + seg * 16);           \
        }                                                                          \
    }

    LOAD_TILE(0, 0); CP_COMMIT();
    LOAD_TILE(1, 1); CP_COMMIT();

    const int lrow = lane & 15;
    const int lhalf = lane >> 4;                     // 0/1 -> +16B column

    int st = 0;
    for (int c = 0; c < NCH; c++) {
        CP_WAIT(1);
        __syncthreads();

        if (c + 2 < NCH) {
            int st2 = (st + 2 >= 3) ? st - 1 : st + 2;
            LOAD_TILE(c + 2, st2);
        }
        CP_COMMIT();

        uint32_t abase = sA0 + st * STB;
        uint32_t bbase = sB0 + st * STB;
#pragma unroll
        for (int kg = 0; kg < 2; kg++) {
            uint32_t a[4][4], b[2][4];
            int lseg = kg * 2 + lhalf;
#pragma unroll
            for (int mt = 0; mt < 4; mt++) {
                int row = wm*64 + mt*16 + lrow;
                ldsm4(a[mt], abase + (uint32_t)(row * 64 + (lseg ^ ((row >> 1) & 3)) * 16));
            }
#pragma unroll
            for (int p = 0; p < 2; p++) {
                int row = wn*32 + p*16 + lrow;
                ldsm4(b[p], bbase + (uint32_t)(row * 64 + (lseg ^ ((row >> 1) & 3)) * 16));
            }
#pragma unroll
            for (int mt = 0; mt < 4; mt++)
#pragma unroll
                for (int nt = 0; nt < 4; nt++) {
                    int p = nt >> 1, q = nt & 1;
                    mma16816(acc[mt][nt], a[mt], b[p][q], b[p][q + 2]);
                }
        }
        st = (st + 1 >= 3) ? 0 : st + 1;
    }

#pragma unroll
    for (int mt = 0; mt < 4; mt++) {
#pragma unroll
        for (int nt = 0; nt < 4; nt++) {
            int m0 = bm * 128 + wm * 64 + mt * 16 + (lane >> 2);
            int n0 = bn * 128 + wn * 32 + nt * 8 + 2 * (lane & 3);
            float c0 = acc[mt][nt][0], c1 = acc[mt][nt][1];
            float c2 = acc[mt][nt][2], c3 = acc[mt][nt][3];
            if (EPI == 0) {
                int part = n0 >> 10;
                __half* dh = (part == 0) ? g_Qh : (part == 1) ? g_Kh : g_Vh;
                float scl = (part == 0) ? 0.125f : 1.0f;
                int head = (n0 & 1023) >> 6, d = n0 & 63;
#pragma unroll
                for (int rr = 0; rr < 2; rr++) {
                    int m = m0 + rr * 8;
                    int bi = m >> 11, s = m & (SEQ - 1);
                    float v0 = (rr ? c2 : c0) * scl, v1 = (rr ? c3 : c1) * scl;
                    size_t idx = (((size_t)(bi*NH + head))*SEQ + s)*HD + d;
                    *(uint32_t*)&dh[idx] = pkh2(__float2half_rn(v0), __float2half_rn(v1));
                }
            } else {
                float2 bv = *(const float2*)&bias[n0];
                *(float2*)&Cout[(size_t)m0 * DIM + n0]       = make_float2(c0 + bv.x, c1 + bv.y);
                *(float2*)&Cout[(size_t)(m0 + 8) * DIM + n0] = make_float2(c2 + bv.x, c3 + bv.y);
            }
        }
    }
}

// ---------------------------------------------------------------------------
// HMMA fp16 flash attention (single-pass fp16), now with 3-STAGE KV pipeline:
// loads run 2 chunks ahead (CP_WAIT(1) + prefetch ch+2), hiding L2 latency.
// CTA = 64 queries x one (b,h), 4 warps, 32KB static smem.
// qi remapped longest-first. allowed(q,k) = (k <= q) || (k < 256).
// Q pre-scaled by 1/8. O written fp16, row-major [b*SEQ+row][DIM].
// ---------------------------------------------------------------------------
__global__ __launch_bounds__(128) void attn_mma()
{
    __shared__ __align__(16) __half sQh[64*64];       //  8192 B
    __shared__ __align__(16) __half sKh[3][32*64];    // 12288 B
    __shared__ __align__(16) __half sVh[3][32*64];    // 12288 B => 32 KB

    const int qi  = (SEQ/64 - 1) - blockIdx.x;        // longest first
    const int bh  = blockIdx.y;
    const int b   = bh >> 4, h = bh & 15;
    const int tid = threadIdx.x, w = tid >> 5, lane = tid & 31;
    const int qbase = qi * 64;

    const size_t base = (size_t)bh * SEQ * HD;
    const uint32_t qh0 = smem_u32(sQh);
    const uint32_t kh0 = smem_u32(sKh), vh0 = smem_u32(sVh);
    const uint32_t KVST = 32 * 128;                   // 4096 B per stage

    // group 1: Q tile
    for (int i = tid; i < 512; i += 128) {
        int r = i >> 3, seg = i & 7;
        int pseg = seg ^ (r & 7);
        const char* gq = (const char*)(g_Qh + base + (size_t)(qbase + r) * HD);
        cp16(qh0 + (uint32_t)(r * 128 + pseg * 16), gq + seg * 16);
    }
    CP_COMMIT();

#define LOADKV(ch, st)                                                              \
    {                                                                               \
        int kb = (ch) * 32;                                                         \
        _Pragma("unroll")                                                           \
        for (int i = tid; i < 256; i += 128) {                                      \
            int r = i >> 3, seg = i & 7;                                            \
            int pseg = seg ^ (r & 7);                                               \
            size_t gidx = base + (size_t)(kb + r) * HD;                             \
            uint32_t so = (uint32_t)((st) * KVST + r * 128 + pseg * 16);            \
            cp16(kh0 + so, (const char*)(g_Kh + gidx) + seg * 16);                  \
            cp16(vh0 + so, (const char*)(g_Vh + gidx) + seg * 16);                  \
        }                                                                           \
    }

    const int nch = (qi < 4) ? 8 : 2 * (qi + 1);
    LOADKV(0, 0); CP_COMMIT();                        // group 2
    LOADKV(1, 1); CP_COMMIT();                        // group 3

    float o[8][4];
#pragma unroll
    for (int i = 0; i < 8; i++)
#pragma unroll
        for (int j = 0; j < 4; j++) o[i][j] = 0.f;
    float mi[2] = {-1e30f, -1e30f}, li[2] = {0.f, 0.f};

    const int lrow  = lane & 15;
    const int lhalf = lane >> 4;

    int st = 0;                                       // stage of chunk ch
    for (int ch = 0; ch < nch; ch++) {
        CP_WAIT(1);                                   // chunk ch resident
        __syncthreads();                              // all warps done with ch-1
        if (ch + 2 < nch) {
            int st2 = (st + 2 >= 3) ? st - 1 : st + 2;
            LOADKV(ch + 2, st2);                      // prefetch 2 ahead
        }
        CP_COMMIT();

        const int kbase = ch * 32;
        const uint32_t kvoff = (uint32_t)(st * KVST);

        // ---- S = Qh Kh^T ----
        float s[4][4];
#pragma unroll
        for (int nt = 0; nt < 4; nt++)
#pragma unroll
            for (int j = 0; j < 4; j++) s[nt][j] = 0.f;

#pragma unroll
        for (int kg = 0; kg < 4; kg++) {
            int lseg = kg * 2 + lhalf;
            uint32_t aH[4], bH[2][4];
            {
                int row = w*16 + lrow;
                ldsm4(aH, qh0 + (uint32_t)(row * 128 + (lseg ^ (row & 7)) * 16));
            }
#pragma unroll
            for (int p = 0; p < 2; p++) {
                int row = p*16 + lrow;
                ldsm4(bH[p], kh0 + kvoff + (uint32_t)(row * 128 + (lseg ^ (row & 7)) * 16));
            }
#pragma unroll
            for (int nt = 0; nt < 4; nt++) {
                int p = nt >> 1, q = nt & 1;
                mma16816(s[nt], aH, bH[p][q], bH[p][q+2]);
            }
        }

        if (kbase >= PREFIX && kbase + 31 > qbase) {
            int q0 = qbase + w*16 + (lane >> 2);
#pragma unroll
            for (int nt = 0; nt < 4; nt++) {
                int k0 = kbase + nt*8 + 2*(lane & 3);
                if (k0     > q0)     s[nt][0] = -1e30f;
                if (k0 + 1 > q0)     s[nt][1] = -1e30f;
                if (k0     > q0 + 8) s[nt][2] = -1e30f;
                if (k0 + 1 > q0 + 8) s[nt][3] = -1e30f;
            }
        }

        // ---- online softmax (rows r and r+8), quad shfl reductions ----
#pragma unroll
        for (int rr = 0; rr < 2; rr++) {
            float mx = -1e30f;
#pragma unroll
            for (int nt = 0; nt < 4; nt++)
                mx = fmaxf(mx, fmaxf(s[nt][2*rr], s[nt][2*rr+1]));
            mx = fmaxf(mx, __shfl_xor_sync(0xffffffffu, mx, 1));
            mx = fmaxf(mx, __shfl_xor_sync(0xffffffffu, mx, 2));
            float mnew  = fmaxf(mi[rr], mx);
            float alpha = __expf(mi[rr] - mnew);
            float rs = 0.f;
#pragma unroll
            for (int nt = 0; nt < 4; nt++) {
                float p0 = __expf(s[nt][2*rr]   - mnew);
                float p1 = __expf(s[nt][2*rr+1] - mnew);
                s[nt][2*rr] = p0; s[nt][2*rr+1] = p1;
                rs += p0 + p1;
            }
            rs += __shfl_xor_sync(0xffffffffu, rs, 1);
            rs += __shfl_xor_sync(0xffffffffu, rs, 2);
            li[rr] = li[rr] * alpha + rs;
            mi[rr] = mnew;
#pragma unroll
            for (int dn = 0; dn < 8; dn++) {
                o[dn][2*rr] *= alpha; o[dn][2*rr+1] *= alpha;
            }
        }

        // ---- O += Ph Vh ----
#pragma unroll
        for (int kt = 0; kt < 2; kt++) {
            uint32_t pH[4];
#pragma unroll
            for (int half = 0; half < 2; half++) {
                float* sv = s[2*kt + half];
                pH[half*2+0] = pkh2(__float2half_rn(sv[0]), __float2half_rn(sv[1]));
                pH[half*2+1] = pkh2(__float2half_rn(sv[2]), __float2half_rn(sv[3]));
            }
#pragma unroll
            for (int p4 = 0; p4 < 4; p4++) {
                int row = kt*16 + lrow;
                int lseg = p4*2 + lhalf;
                uint32_t vo = kvoff + (uint32_t)(row * 128 + (lseg ^ (row & 7)) * 16);
                uint32_t vH[4];
                ldsm4t(vH, vh0 + vo);
                mma16816(o[2*p4],   pH, vH[0], vH[1]);
                mma16816(o[2*p4+1], pH, vH[2], vH[3]);
            }
        }
        st = (st + 1 >= 3) ? 0 : st + 1;
    }

    // ---- epilogue: normalize, write O fp16 [b*SEQ+row][DIM] ----
#pragma unroll
    for (int dn = 0; dn < 8; dn++) {
        int d0 = dn*8 + 2*(lane & 3);
#pragma unroll
        for (int rr = 0; rr < 2; rr++) {
            int row = qbase + w*16 + (lane >> 2) + rr*8;
            float inv = 1.0f / li[rr];
            __half h0 = __float2half_rn(o[dn][2*rr]   * inv);
            __half h1 = __float2half_rn(o[dn][2*rr+1] * inv);
            size_t off = (size_t)(b*SEQ + row) * DIM + (h*HD + d0);
            *(uint32_t*)&g_o16[off] = pkh2(h0, h1);
        }
    }
}

// ---------------------------------------------------------------------------
extern "C" void kernel_launch(void* const* d_in, const int* in_sizes, int n_in,
                              void* d_out, int out_size)
{
    const float* x      = (const float*)d_in[0];
    const float* qkv_w  = (const float*)d_in[1];
    const float* proj_w = (const float*)d_in[2];
    const float* proj_b = (const float*)d_in[3];
    float*       out    = (float*)d_out;

    void *px16, *pw16, *po16, *ppw16;
    cudaGetSymbolAddress(&px16,  g_x16);
    cudaGetSymbolAddress(&pw16,  g_w16);
    cudaGetSymbolAddress(&po16,  g_o16);
    cudaGetSymbolAddress(&ppw16, g_pw16);

    // 0) all three fp32->fp16 conversions in ONE launch
    cvt_all_kernel<<<(CVT_N1+CVT_N2+CVT_N3 + 255)/256, 256>>>(x, qkv_w, proj_w);

    // 1) QKV projection (fp16 HMMA): M=4096, N=3072, K=1024
    mma_gemm<0><<<dim3(3*DIM/128, MROWS/128), 256>>>(
        (const __half*)px16, (const __half*)pw16, nullptr, nullptr);

    // 2) flash attention (fp16 single-pass, 3-stage KV pipeline)
    attn_mma<<<dim3(SEQ/64, BS*NH), 128>>>();

    // 3) proj GEMM + bias: M=4096, N=1024, K=1024
    mma_gemm<1><<<dim3(DIM/128, MROWS/128), 256>>>(
        (const __half*)po16, (const __half*)ppw16, proj_b, out);
}

// round 16
// speedup vs baseline: 2.8359x; 1.0471x over previous
#include <cuda_runtime.h>
#include <cuda_fp16.h>
#include <cstdint>

#define BS   2
#define SEQ  2048
#define DIM  1024
#define NH   16
#define HD   64
#define PREFIX 256
#define MROWS (BS*SEQ)
#define KT   DIM              // plain fp16 GEMM K

// ------------------------- device scratch (no allocs) -----------------------
__device__ __half g_Qh[BS*NH*SEQ*HD];
__device__ __half g_Kh[BS*NH*SEQ*HD];
__device__ __half g_Vh[BS*NH*SEQ*HD];
__device__ __half g_x16 [MROWS*DIM];     // x fp16        (4096 x 1024)
__device__ __half g_w16 [3*DIM*DIM];     // qkv_w fp16    (3072 x 1024)
__device__ __half g_o16 [MROWS*DIM];     // attn out fp16 (4096 x 1024)
__device__ __half g_pw16[DIM*DIM];       // proj_w fp16   (1024 x 1024)

// ------------------------- portable PTX helpers (sm_80+) --------------------
__device__ __forceinline__ uint32_t smem_u32(const void* p) {
    uint32_t a;
    asm("{ .reg .u64 t; cvta.to.shared.u64 t, %1; cvt.u32.u64 %0, t; }" : "=r"(a) : "l"(p));
    return a;
}
__device__ __forceinline__ void cp16(uint32_t saddr, const void* g) {
    asm volatile("cp.async.cg.shared.global [%0], [%1], 16;" :: "r"(saddr), "l"(g));
}
#define CP_COMMIT()  asm volatile("cp.async.commit_group;" ::: "memory")
#define CP_WAIT(n)   asm volatile("cp.async.wait_group %0;" :: "n"(n) : "memory")

__device__ __forceinline__ void ldsm4(uint32_t* r, uint32_t addr) {
    asm volatile("ldmatrix.sync.aligned.m8n8.x4.shared.b16 {%0,%1,%2,%3}, [%4];"
                 : "=r"(r[0]), "=r"(r[1]), "=r"(r[2]), "=r"(r[3]) : "r"(addr));
}
__device__ __forceinline__ void ldsm4t(uint32_t* r, uint32_t addr) {
    asm volatile("ldmatrix.sync.aligned.m8n8.x4.trans.shared.b16 {%0,%1,%2,%3}, [%4];"
                 : "=r"(r[0]), "=r"(r[1]), "=r"(r[2]), "=r"(r[3]) : "r"(addr));
}
__device__ __forceinline__ void mma16816(float* c, const uint32_t* a, uint32_t b0, uint32_t b1) {
    asm volatile("mma.sync.aligned.m16n8k16.row.col.f32.f16.f16.f32 "
                 "{%0,%1,%2,%3}, {%4,%5,%6,%7}, {%8,%9}, {%0,%1,%2,%3};"
                 : "+f"(c[0]), "+f"(c[1]), "+f"(c[2]), "+f"(c[3])
                 : "r"(a[0]), "r"(a[1]), "r"(a[2]), "r"(a[3]), "r"(b0), "r"(b1));
}
__device__ __forceinline__ uint32_t pkh2(__half a, __half b) {
    __half2 t; t.x = a; t.y = b;
    return *(uint32_t*)&t;
}

// ---------------------------------------------------------------------------
// merged fp32 -> fp16 conversion for x, qkv_w, proj_w in ONE launch.
// ---------------------------------------------------------------------------
#define CVT_N1 (MROWS*DIM/4)
#define CVT_N2 (3*DIM*DIM/4)
#define CVT_N3 (DIM*DIM/4)
__global__ __launch_bounds__(256) void cvt_all_kernel(const float* __restrict__ x,
                                                      const float* __restrict__ w,
                                                      const float* __restrict__ pw)
{
    int i = blockIdx.x * blockDim.x + threadIdx.x;
    const float* src;
    __half* dst;
    int j;
    if (i < CVT_N1)                    { src = x;  dst = g_x16;  j = i; }
    else if (i < CVT_N1 + CVT_N2)      { src = w;  dst = g_w16;  j = i - CVT_N1; }
    else if (i < CVT_N1+CVT_N2+CVT_N3) { src = pw; dst = g_pw16; j = i - CVT_N1 - CVT_N2; }
    else return;
    float4 v = ((const float4*)src)[j];
    __half t[4];
    t[0] = __float2half_rn(v.x); t[1] = __float2half_rn(v.y);
    t[2] = __float2half_rn(v.z); t[3] = __float2half_rn(v.w);
    *(uint2*)(dst + (size_t)j * 4) = *(const uint2*)t;
}

// ---------------------------------------------------------------------------
// HMMA fp16 GEMM (UNCHANGED — at mma.sync ceiling).
// ---------------------------------------------------------------------------
template<int EPI>
__global__ __launch_bounds__(256, 2) void mma_gemm(const __half* __restrict__ A2,
                                                   const __half* __restrict__ B2,
                                                   const float* __restrict__ bias,
                                                   float* __restrict__ Cout)
{
    __shared__ __align__(16) __half sA[3][128*32];   // 8192 B / stage
    __shared__ __align__(16) __half sB[3][128*32];

    const int tid  = threadIdx.x;
    const int wid  = tid >> 5, lane = tid & 31;
    const int wm   = wid & 1,  wn   = wid >> 1;      // 2x4 warp grid
    const int bn   = blockIdx.x, bm = blockIdx.y;
    const int NCH  = KT / 32;                        // 32 chunks
    const uint32_t STB = 128 * 64;                   // stage bytes = 8192

    const char* Ab = (const char*)(A2 + (size_t)bm * 128 * KT);
    const char* Bb = (const char*)(B2 + (size_t)bn * 128 * KT);

    const uint32_t sA0 = smem_u32(&sA[0][0]);
    const uint32_t sB0 = smem_u32(&sB[0][0]);

    float acc[4][4][4];
#pragma unroll
    for (int i = 0; i < 4; i++)
#pragma unroll
        for (int j = 0; j < 4; j++)
#pragma unroll
            for (int k = 0; k < 4; k++) acc[i][j][k] = 0.f;

#define LOAD_TILE(c, st)                                                           \
    {                                                                              \
        int koff = (c) * 64;                                                       \
        _Pragma("unroll")                                                          \
        for (int i = 0; i < 2; i++) {                                              \
            int idx = tid + i * 256;                                               \
            int row = idx >> 2, seg = idx & 3;                                     \
            int pseg = seg ^ ((row >> 1) & 3);                                     \
            uint32_t so = (uint32_t)((st) * STB + row * 64 + pseg * 16);           \
            cp16(sA0 + so, Ab + (size_t)row * (KT*2) + koff + seg * 16);           \
            cp16(sB0 + so, Bb + (size_t)row * (KT*2) + koff + seg * 16);           \
        }                                                                          \
    }

    LOAD_TILE(0, 0); CP_COMMIT();
    LOAD_TILE(1, 1); CP_COMMIT();

    const int lrow = lane & 15;
    const int lhalf = lane >> 4;                     // 0/1 -> +16B column

    int st = 0;
    for (int c = 0; c < NCH; c++) {
        CP_WAIT(1);
        __syncthreads();

        if (c + 2 < NCH) {
            int st2 = (st + 2 >= 3) ? st - 1 : st + 2;
            LOAD_TILE(c + 2, st2);
        }
        CP_COMMIT();

        uint32_t abase = sA0 + st * STB;
        uint32_t bbase = sB0 + st * STB;
#pragma unroll
        for (int kg = 0; kg < 2; kg++) {
            uint32_t a[4][4], b[2][4];
            int lseg = kg * 2 + lhalf;
#pragma unroll
            for (int mt = 0; mt < 4; mt++) {
                int row = wm*64 + mt*16 + lrow;
                ldsm4(a[mt], abase + (uint32_t)(row * 64 + (lseg ^ ((row >> 1) & 3)) * 16));
            }
#pragma unroll
            for (int p = 0; p < 2; p++) {
                int row = wn*32 + p*16 + lrow;
                ldsm4(b[p], bbase + (uint32_t)(row * 64 + (lseg ^ ((row >> 1) & 3)) * 16));
            }
#pragma unroll
            for (int mt = 0; mt < 4; mt++)
#pragma unroll
                for (int nt = 0; nt < 4; nt++) {
                    int p = nt >> 1, q = nt & 1;
                    mma16816(acc[mt][nt], a[mt], b[p][q], b[p][q + 2]);
                }
        }
        st = (st + 1 >= 3) ? 0 : st + 1;
    }

#pragma unroll
    for (int mt = 0; mt < 4; mt++) {
#pragma unroll
        for (int nt = 0; nt < 4; nt++) {
            int m0 = bm * 128 + wm * 64 + mt * 16 + (lane >> 2);
            int n0 = bn * 128 + wn * 32 + nt * 8 + 2 * (lane & 3);
            float c0 = acc[mt][nt][0], c1 = acc[mt][nt][1];
            float c2 = acc[mt][nt][2], c3 = acc[mt][nt][3];
            if (EPI == 0) {
                int part = n0 >> 10;
                __half* dh = (part == 0) ? g_Qh : (part == 1) ? g_Kh : g_Vh;
                float scl = (part == 0) ? 0.125f : 1.0f;
                int head = (n0 & 1023) >> 6, d = n0 & 63;
#pragma unroll
                for (int rr = 0; rr < 2; rr++) {
                    int m = m0 + rr * 8;
                    int bi = m >> 11, s = m & (SEQ - 1);
                    float v0 = (rr ? c2 : c0) * scl, v1 = (rr ? c3 : c1) * scl;
                    size_t idx = (((size_t)(bi*NH + head))*SEQ + s)*HD + d;
                    *(uint32_t*)&dh[idx] = pkh2(__float2half_rn(v0), __float2half_rn(v1));
                }
            } else {
                float2 bv = *(const float2*)&bias[n0];
                *(float2*)&Cout[(size_t)m0 * DIM + n0]       = make_float2(c0 + bv.x, c1 + bv.y);
                *(float2*)&Cout[(size_t)(m0 + 8) * DIM + n0] = make_float2(c2 + bv.x, c3 + bv.y);
            }
        }
    }
}

// ---------------------------------------------------------------------------
// HMMA fp16 flash attention with 64-KEY CHUNKS (fixed overheads halved).
// CTA = 64 queries x one (b,h), 4 warps, 2-stage cp.async KV, 40KB smem.
// qi remapped longest-first. allowed(q,k) = (k <= q) || (k < 256).
// Q pre-scaled by 1/8. O written fp16, row-major [b*SEQ+row][DIM].
// ---------------------------------------------------------------------------
__global__ __launch_bounds__(128) void attn_mma()
{
    __shared__ __align__(16) __half sQh[64*64];       //  8192 B
    __shared__ __align__(16) __half sKh[2][64*64];    // 16384 B
    __shared__ __align__(16) __half sVh[2][64*64];    // 16384 B => 40 KB

    const int qi  = (SEQ/64 - 1) - blockIdx.x;        // longest first
    const int bh  = blockIdx.y;
    const int b   = bh >> 4, h = bh & 15;
    const int tid = threadIdx.x, w = tid >> 5, lane = tid & 31;
    const int qbase = qi * 64;

    const size_t base = (size_t)bh * SEQ * HD;
    const uint32_t qh0 = smem_u32(sQh);
    const uint32_t kh0 = smem_u32(sKh), vh0 = smem_u32(sVh);
    const uint32_t KVST = 64 * 128;                   // 8192 B per stage

    // Q tile
    for (int i = tid; i < 512; i += 128) {
        int r = i >> 3, seg = i & 7;
        int pseg = seg ^ (r & 7);
        const char* gq = (const char*)(g_Qh + base + (size_t)(qbase + r) * HD);
        cp16(qh0 + (uint32_t)(r * 128 + pseg * 16), gq + seg * 16);
    }
    CP_COMMIT();

#define LOADKV(ch, st)                                                              \
    {                                                                               \
        int kb = (ch) * 64;                                                         \
        _Pragma("unroll")                                                           \
        for (int i = tid; i < 512; i += 128) {                                      \
            int r = i >> 3, seg = i & 7;                                            \
            int pseg = seg ^ (r & 7);                                               \
            size_t gidx = base + (size_t)(kb + r) * HD;                             \
            uint32_t so = (uint32_t)((st) * KVST + r * 128 + pseg * 16);            \
            cp16(kh0 + so, (const char*)(g_Kh + gidx) + seg * 16);                  \
            cp16(vh0 + so, (const char*)(g_Vh + gidx) + seg * 16);                  \
        }                                                                           \
    }

    const int nch = (qi < 4) ? 4 : (qi + 1);          // 64-key chunks
    LOADKV(0, 0); CP_COMMIT();

    float o[8][4];
#pragma unroll
    for (int i = 0; i < 8; i++)
#pragma unroll
        for (int j = 0; j < 4; j++) o[i][j] = 0.f;
    float mi[2] = {-1e30f, -1e30f}, li[2] = {0.f, 0.f};

    const int lrow  = lane & 15;
    const int lhalf = lane >> 4;

    for (int ch = 0; ch < nch; ch++) {
        CP_WAIT(0);                                   // chunk ch (+Q first time)
        __syncthreads();                              // all warps done with ch-1
        if (ch + 1 < nch) { LOADKV(ch + 1, (ch + 1) & 1); }
        CP_COMMIT();

        const int kbase = ch * 64;
        const uint32_t kvoff = (uint32_t)((ch & 1) * KVST);

        // ---- S = Qh Kh^T : 8 n-tiles of 8 keys ----
        float s[8][4];
#pragma unroll
        for (int nt = 0; nt < 8; nt++)
#pragma unroll
            for (int j = 0; j < 4; j++) s[nt][j] = 0.f;

#pragma unroll
        for (int kg = 0; kg < 4; kg++) {
            int lseg = kg * 2 + lhalf;
            uint32_t aH[4], bH[4][4];
            {
                int row = w*16 + lrow;
                ldsm4(aH, qh0 + (uint32_t)(row * 128 + (lseg ^ (row & 7)) * 16));
            }
#pragma unroll
            for (int p = 0; p < 4; p++) {
                int row = p*16 + lrow;
                ldsm4(bH[p], kh0 + kvoff + (uint32_t)(row * 128 + (lseg ^ (row & 7)) * 16));
            }
#pragma unroll
            for (int nt = 0; nt < 8; nt++) {
                int p = nt >> 1, q = nt & 1;
                mma16816(s[nt], aH, bH[p][q], bH[p][q+2]);
            }
        }

        // ---- causal mask: only the diagonal chunk outside the prefix ----
        if (kbase >= PREFIX && kbase + 63 > qbase) {
            int q0 = qbase + w*16 + (lane >> 2);
#pragma unroll
            for (int nt = 0; nt < 8; nt++) {
                int k0 = kbase + nt*8 + 2*(lane & 3);
                if (k0     > q0)     s[nt][0] = -1e30f;
                if (k0 + 1 > q0)     s[nt][1] = -1e30f;
                if (k0     > q0 + 8) s[nt][2] = -1e30f;
                if (k0 + 1 > q0 + 8) s[nt][3] = -1e30f;
            }
        }

        // ---- online softmax (rows r and r+8), quad shfl reductions ----
#pragma unroll
        for (int rr = 0; rr < 2; rr++) {
            float mx = -1e30f;
#pragma unroll
            for (int nt = 0; nt < 8; nt++)
                mx = fmaxf(mx, fmaxf(s[nt][2*rr], s[nt][2*rr+1]));
            mx = fmaxf(mx, __shfl_xor_sync(0xffffffffu, mx, 1));
            mx = fmaxf(mx, __shfl_xor_sync(0xffffffffu, mx, 2));
            float mnew  = fmaxf(mi[rr], mx);
            float alpha = __expf(mi[rr] - mnew);
            float rs = 0.f;
#pragma unroll
            for (int nt = 0; nt < 8; nt++) {
                float p0 = __expf(s[nt][2*rr]   - mnew);
                float p1 = __expf(s[nt][2*rr+1] - mnew);
                s[nt][2*rr] = p0; s[nt][2*rr+1] = p1;
                rs += p0 + p1;
            }
            rs += __shfl_xor_sync(0xffffffffu, rs, 1);
            rs += __shfl_xor_sync(0xffffffffu, rs, 2);
            li[rr] = li[rr] * alpha + rs;
            mi[rr] = mnew;
#pragma unroll
            for (int dn = 0; dn < 8; dn++) {
                o[dn][2*rr] *= alpha; o[dn][2*rr+1] *= alpha;
            }
        }

        // ---- O += Ph Vh : 4 k-subtiles of 16 keys ----
#pragma unroll
        for (int kt = 0; kt < 4; kt++) {
            uint32_t pH[4];
#pragma unroll
            for (int half = 0; half < 2; half++) {
                float* sv = s[2*kt + half];
                pH[half*2+0] = pkh2(__float2half_rn(sv[0]), __float2half_rn(sv[1]));
                pH[half*2+1] = pkh2(__float2half_rn(sv[2]), __float2half_rn(sv[3]));
            }
#pragma unroll
            for (int p4 = 0; p4 < 4; p4++) {
                int row = kt*16 + lrow;
                int lseg = p4*2 + lhalf;
                uint32_t vo = kvoff + (uint32_t)(row * 128 + (lseg ^ (row & 7)) * 16);
                uint32_t vH[4];
                ldsm4t(vH, vh0 + vo);
                mma16816(o[2*p4],   pH, vH[0], vH[1]);
                mma16816(o[2*p4+1], pH, vH[2], vH[3]);
            }
        }
    }

    // ---- epilogue: normalize, write O fp16 [b*SEQ+row][DIM] ----
#pragma unroll
    for (int dn = 0; dn < 8; dn++) {
        int d0 = dn*8 + 2*(lane & 3);
#pragma unroll
        for (int rr = 0; rr < 2; rr++) {
            int row = qbase + w*16 + (lane >> 2) + rr*8;
            float inv = 1.0f / li[rr];
            __half h0 = __float2half_rn(o[dn][2*rr]   * inv);
            __half h1 = __float2half_rn(o[dn][2*rr+1] * inv);
            size_t off = (size_t)(b*SEQ + row) * DIM + (h*HD + d0);
            *(uint32_t*)&g_o16[off] = pkh2(h0, h1);
        }
    }
}

// ---------------------------------------------------------------------------
extern "C" void kernel_launch(void* const* d_in, const int* in_sizes, int n_in,
                              void* d_out, int out_size)
{
    const float* x      = (const float*)d_in[0];
    const float* qkv_w  = (const float*)d_in[1];
    const float* proj_w = (const float*)d_in[2];
    const float* proj_b = (const float*)d_in[3];
    float*       out    = (float*)d_out;

    void *px16, *pw16, *po16, *ppw16;
    cudaGetSymbolAddress(&px16,  g_x16);
    cudaGetSymbolAddress(&pw16,  g_w16);
    cudaGetSymbolAddress(&po16,  g_o16);
    cudaGetSymbolAddress(&ppw16, g_pw16);

    // 0) all three fp32->fp16 conversions in ONE launch
    cvt_all_kernel<<<(CVT_N1+CVT_N2+CVT_N3 + 255)/256, 256>>>(x, qkv_w, proj_w);

    // 1) QKV projection (fp16 HMMA): M=4096, N=3072, K=1024
    mma_gemm<0><<<dim3(3*DIM/128, MROWS/128), 256>>>(
        (const __half*)px16, (const __half*)pw16, nullptr, nullptr);

    // 2) flash attention (fp16, 64-key chunks)
    attn_mma<<<dim3(SEQ/64, BS*NH), 128>>>();

    // 3) proj GEMM + bias: M=4096, N=1024, K=1024
    mma_gemm<1><<<dim3(DIM/128, MROWS/128), 256>>>(
        (const __half*)po16, (const __half*)ppw16, proj_b, out);
}